// round 1
// baseline (speedup 1.0000x reference)
#include <cuda_runtime.h>
#include <cstdint>
#include <cstddef>

// Problem constants
#define DIMM 1024
#define NSEQ 2048
#define NB   4
#define NH   16
#define HD   64
// scale = DIM^-0.5 = 1/32 (module scales by full dim, not head_dim)
#define ATTN_SCALE 0.03125f

// Scratch (allocation-free rule: __device__ globals)
__device__ float g_qkv[(size_t)NB * NSEQ * 3 * DIMM];   // [b, n, 3*dim] : 96 MB
__device__ float g_att[(size_t)NB * NSEQ * DIMM];       // [b, n, dim]   : 32 MB

// ---------------------------------------------------------------------------
// SGEMM (NT): C[M,N] = A[M,K] * B[N,K]^T (+ optional bias[N])
// A row-major [M,K], B row-major [N,K] (K contiguous for both).
// 128x128 tile, BK=16, 256 threads, 8x8 microtile per thread.
// ---------------------------------------------------------------------------
#define GBM 128
#define GBN 128
#define GBK 16

__global__ __launch_bounds__(256, 2)
void sgemm_nt(const float* __restrict__ A, const float* __restrict__ B,
              float* __restrict__ C, const float* __restrict__ bias,
              int M, int N, int K) {
    __shared__ __align__(16) float As[GBK][GBM + 4];
    __shared__ __align__(16) float Bs[GBK][GBN + 4];

    const int tid = threadIdx.x;
    const int bm = blockIdx.y * GBM;
    const int bn = blockIdx.x * GBN;

    // global-load mapping: 128 rows x 4 float4-cols, two row-halves
    const int lr = tid >> 2;          // 0..63
    const int lc = (tid & 3) * 4;     // 0,4,8,12

    // compute mapping: 16x16 thread grid, 8x8 microtile
    const int tx = tid & 15;
    const int ty = tid >> 4;

    const float* Ag = A + (size_t)(bm + lr) * K + lc;
    const float* Bg = B + (size_t)(bn + lr) * K + lc;

    float acc[8][8];
#pragma unroll
    for (int i = 0; i < 8; i++)
#pragma unroll
        for (int j = 0; j < 8; j++) acc[i][j] = 0.f;

    for (int k0 = 0; k0 < K; k0 += GBK) {
        float4 a0 = *(const float4*)(Ag + k0);
        float4 a1 = *(const float4*)(Ag + (size_t)64 * K + k0);
        float4 b0 = *(const float4*)(Bg + k0);
        float4 b1 = *(const float4*)(Bg + (size_t)64 * K + k0);

        __syncthreads();
        As[lc + 0][lr] = a0.x; As[lc + 1][lr] = a0.y;
        As[lc + 2][lr] = a0.z; As[lc + 3][lr] = a0.w;
        As[lc + 0][lr + 64] = a1.x; As[lc + 1][lr + 64] = a1.y;
        As[lc + 2][lr + 64] = a1.z; As[lc + 3][lr + 64] = a1.w;
        Bs[lc + 0][lr] = b0.x; Bs[lc + 1][lr] = b0.y;
        Bs[lc + 2][lr] = b0.z; Bs[lc + 3][lr] = b0.w;
        Bs[lc + 0][lr + 64] = b1.x; Bs[lc + 1][lr + 64] = b1.y;
        Bs[lc + 2][lr + 64] = b1.z; Bs[lc + 3][lr + 64] = b1.w;
        __syncthreads();

#pragma unroll
        for (int k = 0; k < GBK; k++) {
            float af[8], bf[8];
            *(float4*)(af)     = *(const float4*)&As[k][ty * 8];
            *(float4*)(af + 4) = *(const float4*)&As[k][ty * 8 + 4];
            *(float4*)(bf)     = *(const float4*)&Bs[k][tx * 8];
            *(float4*)(bf + 4) = *(const float4*)&Bs[k][tx * 8 + 4];
#pragma unroll
            for (int i = 0; i < 8; i++)
#pragma unroll
                for (int j = 0; j < 8; j++)
                    acc[i][j] += af[i] * bf[j];
        }
    }

    // epilogue
    float bv[8];
    if (bias) {
#pragma unroll
        for (int j = 0; j < 8; j++) bv[j] = bias[bn + tx * 8 + j];
    } else {
#pragma unroll
        for (int j = 0; j < 8; j++) bv[j] = 0.f;
    }
#pragma unroll
    for (int i = 0; i < 8; i++) {
        float* Cr = C + (size_t)(bm + ty * 8 + i) * N + bn + tx * 8;
        float4 c0 = make_float4(acc[i][0] + bv[0], acc[i][1] + bv[1],
                                acc[i][2] + bv[2], acc[i][3] + bv[3]);
        float4 c1 = make_float4(acc[i][4] + bv[4], acc[i][5] + bv[5],
                                acc[i][6] + bv[6], acc[i][7] + bv[7]);
        *(float4*)(Cr)     = c0;
        *(float4*)(Cr + 4) = c1;
    }
}

// ---------------------------------------------------------------------------
// Flash attention (fp32, streaming softmax).
// qkv layout: [b, n, 3*dim] where feature e = which*1024 + h*64 + d.
// Grid: (NSEQ/64, NH, NB). Block: 256 threads.
// Thread t: q-row r = t>>2, c = t&3.
//   S ownership (interleaved): j = 4*jj + c, jj in 0..7  (BLK_K = 32)
//   O ownership (blocked):     d = c*16 + i, i in 0..15
// ---------------------------------------------------------------------------
#define BQ 64
#define BKV 32
#define QPAD 68

__global__ __launch_bounds__(256)
void flash_attn(const float* __restrict__ qkv, float* __restrict__ out) {
    __shared__ __align__(16) float Qs[BQ][QPAD];
    __shared__ __align__(16) float Ks[BKV][QPAD];
    __shared__ __align__(16) float Vs[BKV][QPAD];

    const int tid = threadIdx.x;
    const int qb = blockIdx.x;   // 0..31
    const int h  = blockIdx.y;   // 0..15
    const int b  = blockIdx.z;   // 0..3

    const size_t rowstride = 3 * DIMM;  // 3072
    const float* Qg = qkv + ((size_t)b * NSEQ + (size_t)qb * BQ) * rowstride + h * HD;
    const float* Kg = qkv + (size_t)b * NSEQ * rowstride + DIMM + h * HD;
    const float* Vg = Kg + DIMM;

    // Load Q tile (pre-scaled): 64 rows x 16 float4 = 1024 float4, 4/thread
#pragma unroll
    for (int i = 0; i < 4; i++) {
        int idx = tid + i * 256;
        int row = idx >> 4;
        int c4  = (idx & 15) * 4;
        float4 v = *(const float4*)(Qg + (size_t)row * rowstride + c4);
        Qs[row][c4 + 0] = v.x * ATTN_SCALE;
        Qs[row][c4 + 1] = v.y * ATTN_SCALE;
        Qs[row][c4 + 2] = v.z * ATTN_SCALE;
        Qs[row][c4 + 3] = v.w * ATTN_SCALE;
    }

    const int r = tid >> 2;
    const int c = tid & 3;

    float m = -1e30f;
    float l = 0.f;
    float o[16];
#pragma unroll
    for (int i = 0; i < 16; i++) o[i] = 0.f;

    for (int kt = 0; kt < NSEQ / BKV; kt++) {
        __syncthreads();   // previous tile's smem reads done (also orders Q load)
        // Load K,V tile: 32 rows x 16 float4 each; 2/thread each
#pragma unroll
        for (int i = 0; i < 2; i++) {
            int idx = tid + i * 256;
            int row = idx >> 4;
            int c4  = (idx & 15) * 4;
            const size_t go = (size_t)(kt * BKV + row) * rowstride + c4;
            float4 kv = *(const float4*)(Kg + go);
            float4 vv = *(const float4*)(Vg + go);
            *(float4*)&Ks[row][c4] = kv;
            *(float4*)&Vs[row][c4] = vv;
        }
        __syncthreads();

        // S[r][4*jj + c] = Qs[r,:] . Ks[4*jj+c,:]
        float s[8];
#pragma unroll
        for (int jj = 0; jj < 8; jj++) s[jj] = 0.f;
#pragma unroll
        for (int k4 = 0; k4 < 16; k4++) {
            float4 q4 = *(const float4*)&Qs[r][k4 * 4];
#pragma unroll
            for (int jj = 0; jj < 8; jj++) {
                float4 kk = *(const float4*)&Ks[jj * 4 + c][k4 * 4];
                s[jj] += q4.x * kk.x + q4.y * kk.y + q4.z * kk.z + q4.w * kk.w;
            }
        }

        // row max across the 4-thread group
        float mt = s[0];
#pragma unroll
        for (int jj = 1; jj < 8; jj++) mt = fmaxf(mt, s[jj]);
        mt = fmaxf(mt, __shfl_xor_sync(0xffffffffu, mt, 1));
        mt = fmaxf(mt, __shfl_xor_sync(0xffffffffu, mt, 2));

        float mn = fmaxf(m, mt);
        float alpha = __expf(m - mn);

        float p[8];
        float ps = 0.f;
#pragma unroll
        for (int jj = 0; jj < 8; jj++) {
            p[jj] = __expf(s[jj] - mn);
            ps += p[jj];
        }
        ps += __shfl_xor_sync(0xffffffffu, ps, 1);
        ps += __shfl_xor_sync(0xffffffffu, ps, 2);

        l = l * alpha + ps;
        m = mn;
#pragma unroll
        for (int i = 0; i < 16; i++) o[i] *= alpha;

        // O[r][c*16 + i] += sum_j P[r][j] * Vs[j][c*16 + i]
#pragma unroll
        for (int j = 0; j < BKV; j++) {
            // owner lane of P[r][j]: same 4-group, lane = (tid&28) | (j&3), slot j>>2
            float pj = __shfl_sync(0xffffffffu, p[j >> 2], (tid & 28) | (j & 3));
            float4 v0 = *(const float4*)&Vs[j][c * 16 + 0];
            float4 v1 = *(const float4*)&Vs[j][c * 16 + 4];
            float4 v2 = *(const float4*)&Vs[j][c * 16 + 8];
            float4 v3 = *(const float4*)&Vs[j][c * 16 + 12];
            o[0]  += pj * v0.x; o[1]  += pj * v0.y; o[2]  += pj * v0.z; o[3]  += pj * v0.w;
            o[4]  += pj * v1.x; o[5]  += pj * v1.y; o[6]  += pj * v1.z; o[7]  += pj * v1.w;
            o[8]  += pj * v2.x; o[9]  += pj * v2.y; o[10] += pj * v2.z; o[11] += pj * v2.w;
            o[12] += pj * v3.x; o[13] += pj * v3.y; o[14] += pj * v3.z; o[15] += pj * v3.w;
        }
    }

    float inv = 1.f / l;
    float* og = out + ((size_t)b * NSEQ + (size_t)qb * BQ + r) * DIMM + h * HD + c * 16;
#pragma unroll
    for (int i4 = 0; i4 < 4; i4++) {
        float4 w = make_float4(o[i4 * 4 + 0] * inv, o[i4 * 4 + 1] * inv,
                               o[i4 * 4 + 2] * inv, o[i4 * 4 + 3] * inv);
        *(float4*)(og + i4 * 4) = w;
    }
}

// ---------------------------------------------------------------------------
// Launch: qkv-proj GEMM -> flash attention -> out-proj GEMM (+bias)
// ---------------------------------------------------------------------------
extern "C" void kernel_launch(void* const* d_in, const int* in_sizes, int n_in,
                              void* d_out, int out_size) {
    const float* x     = (const float*)d_in[0];  // [4, 2048, 1024]
    const float* w_qkv = (const float*)d_in[1];  // [3072, 1024]
    const float* w_out = (const float*)d_in[2];  // [1024, 1024]
    const float* b_out = (const float*)d_in[3];  // [1024]
    float* out = (float*)d_out;                  // [4, 2048, 1024]

    float* qkv_buf = nullptr;
    float* att_buf = nullptr;
    cudaGetSymbolAddress((void**)&qkv_buf, g_qkv);
    cudaGetSymbolAddress((void**)&att_buf, g_att);

    const int M = NB * NSEQ;  // 8192

    // 1) qkv = x @ w_qkv^T : [8192, 3072]
    {
        dim3 grid(3 * DIMM / GBN, M / GBM);  // (24, 64)
        sgemm_nt<<<grid, 256>>>(x, w_qkv, qkv_buf, nullptr, M, 3 * DIMM, DIMM);
    }

    // 2) flash attention: att = softmax(Q K^T * scale) V  -> [b, n, dim]
    {
        dim3 grid(NSEQ / BQ, NH, NB);  // (32, 16, 4)
        flash_attn<<<grid, 256>>>(qkv_buf, att_buf);
    }

    // 3) out = att @ w_out^T + b_out : [8192, 1024]
    {
        dim3 grid(DIMM / GBN, M / GBM);  // (8, 64)
        sgemm_nt<<<grid, 256>>>(att_buf, w_out, out, b_out, M, DIMM, DIMM);
    }
}

// round 2
// speedup vs baseline: 1.0008x; 1.0008x over previous
#include <cuda_runtime.h>
#include <cstdint>
#include <cstddef>

// Problem constants
#define DIMM 1024
#define NSEQ 2048
#define NB   4
#define NH   16
#define HD   64
// scale = DIM^-0.5 = 1/32 (module scales by full dim, not head_dim)
#define ATTN_SCALE 0.03125f

// Scratch (allocation-free rule: __device__ globals)
__device__ float g_qkv[(size_t)NB * NSEQ * 3 * DIMM];   // [b, n, 3*dim] : 96 MB
__device__ float g_att[(size_t)NB * NSEQ * DIMM];       // [b, n, dim]   : 32 MB

// ---------------------------------------------------------------------------
// SGEMM (NT): C[M,N] = A[M,K] * B[N,K]^T (+ optional bias[N])
// A row-major [M,K], B row-major [N,K] (K contiguous for both).
// 128x128 tile, BK=16, 256 threads, 8x8 microtile per thread.
// ---------------------------------------------------------------------------
#define GBM 128
#define GBN 128
#define GBK 16

__global__ __launch_bounds__(256, 2)
void sgemm_nt(const float* __restrict__ A, const float* __restrict__ B,
              float* __restrict__ C, const float* __restrict__ bias,
              int M, int N, int K) {
    __shared__ __align__(16) float As[GBK][GBM + 4];
    __shared__ __align__(16) float Bs[GBK][GBN + 4];

    const int tid = threadIdx.x;
    const int bm = blockIdx.y * GBM;
    const int bn = blockIdx.x * GBN;

    // global-load mapping: 128 rows x 4 float4-cols, two row-halves
    const int lr = tid >> 2;          // 0..63
    const int lc = (tid & 3) * 4;     // 0,4,8,12

    // compute mapping: 16x16 thread grid, 8x8 microtile
    const int tx = tid & 15;
    const int ty = tid >> 4;

    const float* Ag = A + (size_t)(bm + lr) * K + lc;
    const float* Bg = B + (size_t)(bn + lr) * K + lc;

    float acc[8][8];
#pragma unroll
    for (int i = 0; i < 8; i++)
#pragma unroll
        for (int j = 0; j < 8; j++) acc[i][j] = 0.f;

    for (int k0 = 0; k0 < K; k0 += GBK) {
        float4 a0 = *(const float4*)(Ag + k0);
        float4 a1 = *(const float4*)(Ag + (size_t)64 * K + k0);
        float4 b0 = *(const float4*)(Bg + k0);
        float4 b1 = *(const float4*)(Bg + (size_t)64 * K + k0);

        __syncthreads();
        As[lc + 0][lr] = a0.x; As[lc + 1][lr] = a0.y;
        As[lc + 2][lr] = a0.z; As[lc + 3][lr] = a0.w;
        As[lc + 0][lr + 64] = a1.x; As[lc + 1][lr + 64] = a1.y;
        As[lc + 2][lr + 64] = a1.z; As[lc + 3][lr + 64] = a1.w;
        Bs[lc + 0][lr] = b0.x; Bs[lc + 1][lr] = b0.y;
        Bs[lc + 2][lr] = b0.z; Bs[lc + 3][lr] = b0.w;
        Bs[lc + 0][lr + 64] = b1.x; Bs[lc + 1][lr + 64] = b1.y;
        Bs[lc + 2][lr + 64] = b1.z; Bs[lc + 3][lr + 64] = b1.w;
        __syncthreads();

#pragma unroll
        for (int k = 0; k < GBK; k++) {
            float af[8], bf[8];
            *(float4*)(af)     = *(const float4*)&As[k][ty * 8];
            *(float4*)(af + 4) = *(const float4*)&As[k][ty * 8 + 4];
            *(float4*)(bf)     = *(const float4*)&Bs[k][tx * 8];
            *(float4*)(bf + 4) = *(const float4*)&Bs[k][tx * 8 + 4];
#pragma unroll
            for (int i = 0; i < 8; i++)
#pragma unroll
                for (int j = 0; j < 8; j++)
                    acc[i][j] += af[i] * bf[j];
        }
    }

    // epilogue
    float bv[8];
    if (bias) {
#pragma unroll
        for (int j = 0; j < 8; j++) bv[j] = bias[bn + tx * 8 + j];
    } else {
#pragma unroll
        for (int j = 0; j < 8; j++) bv[j] = 0.f;
    }
#pragma unroll
    for (int i = 0; i < 8; i++) {
        float* Cr = C + (size_t)(bm + ty * 8 + i) * N + bn + tx * 8;
        float4 c0 = make_float4(acc[i][0] + bv[0], acc[i][1] + bv[1],
                                acc[i][2] + bv[2], acc[i][3] + bv[3]);
        float4 c1 = make_float4(acc[i][4] + bv[4], acc[i][5] + bv[5],
                                acc[i][6] + bv[6], acc[i][7] + bv[7]);
        *(float4*)(Cr)     = c0;
        *(float4*)(Cr + 4) = c1;
    }
}

// ---------------------------------------------------------------------------
// Flash attention (fp32, streaming softmax).
// qkv layout: [b, n, 3*dim] where feature e = which*1024 + h*64 + d.
// Grid: (NSEQ/64, NH, NB). Block: 256 threads.
// Thread t: q-row r = t>>2, c = t&3.
//   S ownership (interleaved): j = 4*jj + c, jj in 0..7  (BLK_K = 32)
//   O ownership (blocked):     d = c*16 + i, i in 0..15
// ---------------------------------------------------------------------------
#define BQ 64
#define BKV 32
#define QPAD 68

__global__ __launch_bounds__(256)
void flash_attn(const float* __restrict__ qkv, float* __restrict__ out) {
    __shared__ __align__(16) float Qs[BQ][QPAD];
    __shared__ __align__(16) float Ks[BKV][QPAD];
    __shared__ __align__(16) float Vs[BKV][QPAD];

    const int tid = threadIdx.x;
    const int qb = blockIdx.x;   // 0..31
    const int h  = blockIdx.y;   // 0..15
    const int b  = blockIdx.z;   // 0..3

    const size_t rowstride = 3 * DIMM;  // 3072
    const float* Qg = qkv + ((size_t)b * NSEQ + (size_t)qb * BQ) * rowstride + h * HD;
    const float* Kg = qkv + (size_t)b * NSEQ * rowstride + DIMM + h * HD;
    const float* Vg = Kg + DIMM;

    // Load Q tile (pre-scaled): 64 rows x 16 float4 = 1024 float4, 4/thread
#pragma unroll
    for (int i = 0; i < 4; i++) {
        int idx = tid + i * 256;
        int row = idx >> 4;
        int c4  = (idx & 15) * 4;
        float4 v = *(const float4*)(Qg + (size_t)row * rowstride + c4);
        Qs[row][c4 + 0] = v.x * ATTN_SCALE;
        Qs[row][c4 + 1] = v.y * ATTN_SCALE;
        Qs[row][c4 + 2] = v.z * ATTN_SCALE;
        Qs[row][c4 + 3] = v.w * ATTN_SCALE;
    }

    const int r = tid >> 2;
    const int c = tid & 3;

    float m = -1e30f;
    float l = 0.f;
    float o[16];
#pragma unroll
    for (int i = 0; i < 16; i++) o[i] = 0.f;

    for (int kt = 0; kt < NSEQ / BKV; kt++) {
        __syncthreads();   // previous tile's smem reads done (also orders Q load)
        // Load K,V tile: 32 rows x 16 float4 each; 2/thread each
#pragma unroll
        for (int i = 0; i < 2; i++) {
            int idx = tid + i * 256;
            int row = idx >> 4;
            int c4  = (idx & 15) * 4;
            const size_t go = (size_t)(kt * BKV + row) * rowstride + c4;
            float4 kv = *(const float4*)(Kg + go);
            float4 vv = *(const float4*)(Vg + go);
            *(float4*)&Ks[row][c4] = kv;
            *(float4*)&Vs[row][c4] = vv;
        }
        __syncthreads();

        // S[r][4*jj + c] = Qs[r,:] . Ks[4*jj+c,:]
        float s[8];
#pragma unroll
        for (int jj = 0; jj < 8; jj++) s[jj] = 0.f;
#pragma unroll
        for (int k4 = 0; k4 < 16; k4++) {
            float4 q4 = *(const float4*)&Qs[r][k4 * 4];
#pragma unroll
            for (int jj = 0; jj < 8; jj++) {
                float4 kk = *(const float4*)&Ks[jj * 4 + c][k4 * 4];
                s[jj] += q4.x * kk.x + q4.y * kk.y + q4.z * kk.z + q4.w * kk.w;
            }
        }

        // row max across the 4-thread group
        float mt = s[0];
#pragma unroll
        for (int jj = 1; jj < 8; jj++) mt = fmaxf(mt, s[jj]);
        mt = fmaxf(mt, __shfl_xor_sync(0xffffffffu, mt, 1));
        mt = fmaxf(mt, __shfl_xor_sync(0xffffffffu, mt, 2));

        float mn = fmaxf(m, mt);
        float alpha = __expf(m - mn);

        float p[8];
        float ps = 0.f;
#pragma unroll
        for (int jj = 0; jj < 8; jj++) {
            p[jj] = __expf(s[jj] - mn);
            ps += p[jj];
        }
        ps += __shfl_xor_sync(0xffffffffu, ps, 1);
        ps += __shfl_xor_sync(0xffffffffu, ps, 2);

        l = l * alpha + ps;
        m = mn;
#pragma unroll
        for (int i = 0; i < 16; i++) o[i] *= alpha;

        // O[r][c*16 + i] += sum_j P[r][j] * Vs[j][c*16 + i]
#pragma unroll
        for (int j = 0; j < BKV; j++) {
            // owner lane of P[r][j]: same 4-group, lane = (tid&28) | (j&3), slot j>>2
            float pj = __shfl_sync(0xffffffffu, p[j >> 2], (tid & 28) | (j & 3));
            float4 v0 = *(const float4*)&Vs[j][c * 16 + 0];
            float4 v1 = *(const float4*)&Vs[j][c * 16 + 4];
            float4 v2 = *(const float4*)&Vs[j][c * 16 + 8];
            float4 v3 = *(const float4*)&Vs[j][c * 16 + 12];
            o[0]  += pj * v0.x; o[1]  += pj * v0.y; o[2]  += pj * v0.z; o[3]  += pj * v0.w;
            o[4]  += pj * v1.x; o[5]  += pj * v1.y; o[6]  += pj * v1.z; o[7]  += pj * v1.w;
            o[8]  += pj * v2.x; o[9]  += pj * v2.y; o[10] += pj * v2.z; o[11] += pj * v2.w;
            o[12] += pj * v3.x; o[13] += pj * v3.y; o[14] += pj * v3.z; o[15] += pj * v3.w;
        }
    }

    float inv = 1.f / l;
    float* og = out + ((size_t)b * NSEQ + (size_t)qb * BQ + r) * DIMM + h * HD + c * 16;
#pragma unroll
    for (int i4 = 0; i4 < 4; i4++) {
        float4 w = make_float4(o[i4 * 4 + 0] * inv, o[i4 * 4 + 1] * inv,
                               o[i4 * 4 + 2] * inv, o[i4 * 4 + 3] * inv);
        *(float4*)(og + i4 * 4) = w;
    }
}

// ---------------------------------------------------------------------------
// Launch: qkv-proj GEMM -> flash attention -> out-proj GEMM (+bias)
// ---------------------------------------------------------------------------
extern "C" void kernel_launch(void* const* d_in, const int* in_sizes, int n_in,
                              void* d_out, int out_size) {
    const float* x     = (const float*)d_in[0];  // [4, 2048, 1024]
    const float* w_qkv = (const float*)d_in[1];  // [3072, 1024]
    const float* w_out = (const float*)d_in[2];  // [1024, 1024]
    const float* b_out = (const float*)d_in[3];  // [1024]
    float* out = (float*)d_out;                  // [4, 2048, 1024]

    float* qkv_buf = nullptr;
    float* att_buf = nullptr;
    cudaGetSymbolAddress((void**)&qkv_buf, g_qkv);
    cudaGetSymbolAddress((void**)&att_buf, g_att);

    const int M = NB * NSEQ;  // 8192

    // 1) qkv = x @ w_qkv^T : [8192, 3072]
    {
        dim3 grid(3 * DIMM / GBN, M / GBM);  // (24, 64)
        sgemm_nt<<<grid, 256>>>(x, w_qkv, qkv_buf, nullptr, M, 3 * DIMM, DIMM);
    }

    // 2) flash attention: att = softmax(Q K^T * scale) V  -> [b, n, dim]
    {
        dim3 grid(NSEQ / BQ, NH, NB);  // (32, 16, 4)
        flash_attn<<<grid, 256>>>(qkv_buf, att_buf);
    }

    // 3) out = att @ w_out^T + b_out : [8192, 1024]
    {
        dim3 grid(DIMM / GBN, M / GBM);  // (8, 64)
        sgemm_nt<<<grid, 256>>>(att_buf, w_out, out, b_out, M, DIMM, DIMM);
    }
}

// round 4
// speedup vs baseline: 3.5871x; 3.5844x over previous
#include <cuda_runtime.h>
#include <cuda_bf16.h>
#include <cstdint>
#include <cstddef>

#define DIMM 1024
#define NSEQ 2048
#define NB   4
#define NH   16
#define HD   64
#define NBH  (NB*NH)
#define ATTN_SCALE 0.03125f
#define BK 32

typedef __nv_bfloat16 bf16;

__device__ float g_qkv[(size_t)NB*NSEQ*3*DIMM];
__device__ float g_att[(size_t)NB*NSEQ*DIMM];
__device__ float g_S[(size_t)NBH*NSEQ*NSEQ];
__device__ bf16 g_Ph[(size_t)NBH*NSEQ*NSEQ], g_Pl[(size_t)NBH*NSEQ*NSEQ];
__device__ bf16 g_xh[(size_t)NB*NSEQ*DIMM],  g_xl[(size_t)NB*NSEQ*DIMM];
__device__ bf16 g_wqh[(size_t)3*DIMM*DIMM],  g_wql[(size_t)3*DIMM*DIMM];
__device__ bf16 g_woh[(size_t)DIMM*DIMM],    g_wol[(size_t)DIMM*DIMM];
__device__ bf16 g_qh[(size_t)NBH*NSEQ*HD],   g_ql[(size_t)NBH*NSEQ*HD];
__device__ bf16 g_kh[(size_t)NBH*NSEQ*HD],   g_kl[(size_t)NBH*NSEQ*HD];
__device__ bf16 g_vth[(size_t)NBH*HD*NSEQ],  g_vtl[(size_t)NBH*HD*NSEQ];
__device__ bf16 g_ah[(size_t)NB*NSEQ*DIMM],  g_al[(size_t)NB*NSEQ*DIMM];

__device__ __forceinline__ uint32_t s2u(const void* p){
    uint32_t a; asm("{ .reg .u64 t; cvta.to.shared.u64 t, %1; cvt.u32.u64 %0, t; }":"=r"(a):"l"(p)); return a;
}
__device__ __forceinline__ void cp16(uint32_t s, const void* g){
    asm volatile("cp.async.cg.shared.global [%0], [%1], 16;"::"r"(s),"l"(g));
}
#define CPC() asm volatile("cp.async.commit_group;":::"memory")
#define CPW(n) asm volatile("cp.async.wait_group %0;"::"n"(n):"memory")

__device__ __forceinline__ void ldm4(uint32_t* f, uint32_t a){
    asm volatile("ldmatrix.sync.aligned.m8n8.x4.shared.b16 {%0,%1,%2,%3}, [%4];"
        :"=r"(f[0]),"=r"(f[1]),"=r"(f[2]),"=r"(f[3]):"r"(a));
}
__device__ __forceinline__ void mma16816(float* d, const uint32_t* a, uint32_t b0, uint32_t b1){
    asm volatile("mma.sync.aligned.m16n8k16.row.col.f32.bf16.bf16.f32 "
        "{%0,%1,%2,%3}, {%4,%5,%6,%7}, {%8,%9}, {%0,%1,%2,%3};"
        :"+f"(d[0]),"+f"(d[1]),"+f"(d[2]),"+f"(d[3])
        :"r"(a[0]),"r"(a[1]),"r"(a[2]),"r"(a[3]),"r"(b0),"r"(b1));
}
__device__ __forceinline__ void split1(float v, bf16& h, bf16& l){
    h = __float2bfloat16(v); l = __float2bfloat16(v - __bfloat162float(h));
}

// C[z][m][n] = (Ah+Al)[m,:].(Bh+Bl)[n,:] via Ah.Bh + Al.Bh + Ah.Bl
// A [.., K] row-major, B [.., K] row-major (NT). BM=128 x BN tile, BK=32.
template<int BN>
__global__ __launch_bounds__(256, 2)
void gemm3t(const bf16* __restrict__ Ah, const bf16* __restrict__ Al,
            const bf16* __restrict__ Bh, const bf16* __restrict__ Bl,
            float* __restrict__ C, const float* __restrict__ bias,
            int K, int ldc, size_t sAz, size_t sBz, size_t sCz1, size_t sCz2){
    constexpr int NT = (BN==128) ? 8 : 4;     // n8 tiles per warp
    constexpr int WNS = NT*8;                 // warp n-span
    constexpr int STAGE = (128+BN)*BK*2;      // bytes per stage
    __shared__ __align__(256) char smem[2*STAGE];

    const int tid = threadIdx.x, lane = tid&31, warp = tid>>5;
    const int wm = warp&3, wn = warp>>2;      // 4 x 2
    const int bn0 = blockIdx.x*BN, bm0 = blockIdx.y*128, z = blockIdx.z;
    const size_t lda = (size_t)K*2;

    const char* A0 = (const char*)(Ah + (size_t)z*sAz + (size_t)bm0*K);
    const char* A1 = (const char*)(Al + (size_t)z*sAz + (size_t)bm0*K);
    const char* B0 = (const char*)(Bh + (size_t)z*sBz + (size_t)bn0*K);
    const char* B1 = (const char*)(Bl + (size_t)z*sBz + (size_t)bn0*K);
    const int CK = K/BK, T = 3*CK;

    float acc[2][NT][4];
#pragma unroll
    for (int i=0;i<2;i++)
#pragma unroll
        for (int j=0;j<NT;j++)
#pragma unroll
            for (int k=0;k<4;k++) acc[i][j][k] = 0.f;

    auto load = [&](int t, int s){
        const int seg = t/CK, kk = t - seg*CK;
        const char* Ab = ((seg==1)?A1:A0) + (size_t)kk*64;
        const char* Bb = ((seg==2)?B1:B0) + (size_t)kk*64;
        const uint32_t ua = s2u(smem) + s*STAGE;
        const uint32_t ub = ua + 128*BK*2;
#pragma unroll
        for (int i=0;i<2;i++){ int id=tid+i*256, r=id>>2, c=id&3;
            cp16(ua + r*64 + ((c^((r>>1)&3))<<4), Ab + (size_t)r*lda + c*16); }
#pragma unroll
        for (int i=0;i<BN/64;i++){ int id=tid+i*256, r=id>>2, c=id&3;
            cp16(ub + r*64 + ((c^((r>>1)&3))<<4), Bb + (size_t)r*lda + c*16); }
    };

    load(0,0); CPC();
    for (int t=0; t<T; t++){
        const int s = t&1;
        if (t+1<T){ load(t+1, s^1); CPC(); CPW(1); } else { CPW(0); }
        __syncthreads();
        const uint32_t ua = s2u(smem) + s*STAGE;
        const uint32_t ub = ua + 128*BK*2;
        const int q = lane>>3, sub = lane&7;
#pragma unroll
        for (int ks=0; ks<2; ks++){
            uint32_t af[2][4], bfr[NT/2][4];
            const int ch = ks*2 + (q>>1);
#pragma unroll
            for (int mt=0; mt<2; mt++){
                int r = wm*32 + mt*16 + (q&1)*8 + sub;
                ldm4(af[mt], ua + r*64 + ((ch^((r>>1)&3))<<4));
            }
#pragma unroll
            for (int np=0; np<NT/2; np++){
                int r = wn*WNS + np*16 + (q&1)*8 + sub;
                ldm4(bfr[np], ub + r*64 + ((ch^((r>>1)&3))<<4));
            }
#pragma unroll
            for (int mt=0; mt<2; mt++)
#pragma unroll
                for (int nt=0; nt<NT; nt++)
                    mma16816(acc[mt][nt], af[mt], bfr[nt>>1][nt&1], bfr[nt>>1][2+(nt&1)]);
        }
        __syncthreads();
    }

    float* Cb = C + (size_t)(z>>4)*sCz1 + (size_t)(z&15)*sCz2;
#pragma unroll
    for (int mt=0; mt<2; mt++){
        const int m0 = bm0 + wm*32 + mt*16 + (lane>>2);
#pragma unroll
        for (int nt=0; nt<NT; nt++){
            const int n = bn0 + wn*WNS + nt*8 + (lane&3)*2;
            float bx = 0.f, by = 0.f;
            if (bias){ bx = bias[n]; by = bias[n+1]; }
            float2 v0 = {acc[mt][nt][0]+bx, acc[mt][nt][1]+by};
            float2 v1 = {acc[mt][nt][2]+bx, acc[mt][nt][3]+by};
            *(float2*)(Cb + (size_t)m0*ldc + n) = v0;
            *(float2*)(Cb + (size_t)(m0+8)*ldc + n) = v1;
        }
    }
}

__global__ void split_arr(const float* __restrict__ in, bf16* __restrict__ h, bf16* __restrict__ l, int n4){
    int i = blockIdx.x*blockDim.x + threadIdx.x;
    if (i>=n4) return;
    float4 v = ((const float4*)in)[i];
    __align__(8) bf16 hh[4], ll[4];
    split1(v.x,hh[0],ll[0]); split1(v.y,hh[1],ll[1]); split1(v.z,hh[2],ll[2]); split1(v.w,hh[3],ll[3]);
    ((uint2*)h)[i] = *(uint2*)hh; ((uint2*)l)[i] = *(uint2*)ll;
}

__global__ void qkv_split(const float* __restrict__ qkv,
        bf16* __restrict__ qh, bf16* __restrict__ ql, bf16* __restrict__ kh, bf16* __restrict__ kl,
        bf16* __restrict__ vth, bf16* __restrict__ vtl){
    int idx = blockIdx.x*blockDim.x + threadIdx.x;
    int d = idx&63, h = (idx>>6)&15, n = (idx>>10)&2047, b = idx>>21;
    size_t base = ((size_t)(b*NSEQ+n))*(3*DIMM) + h*HD + d;
    size_t qi = (((size_t)(b*NH+h))*NSEQ + n)*HD + d;
    size_t vi = (((size_t)(b*NH+h))*HD + d)*NSEQ + n;
    split1(qkv[base]*ATTN_SCALE, qh[qi], ql[qi]);
    split1(qkv[base+DIMM], kh[qi], kl[qi]);
    split1(qkv[base+2*DIMM], vth[vi], vtl[vi]);
}

__global__ __launch_bounds__(256)
void softmax_rows(const float* __restrict__ S, bf16* __restrict__ Ph, bf16* __restrict__ Pl){
    __shared__ float red[8];
    const int tid = threadIdx.x, wid = tid>>5, lid = tid&31;
    const size_t row = (size_t)blockIdx.y*NSEQ + blockIdx.x;
    const float* s = S + row*NSEQ;
    float x[8];
    *(float4*)x     = *(const float4*)(s + tid*8);
    *(float4*)(x+4) = *(const float4*)(s + tid*8 + 4);
    float m = x[0];
#pragma unroll
    for (int i=1;i<8;i++) m = fmaxf(m, x[i]);
#pragma unroll
    for (int o=16;o;o>>=1) m = fmaxf(m, __shfl_xor_sync(~0u, m, o));
    if (lid==0) red[wid]=m;
    __syncthreads();
    m = red[0];
#pragma unroll
    for (int i=1;i<8;i++) m = fmaxf(m, red[i]);
    __syncthreads();
    float e[8], sum=0.f;
#pragma unroll
    for (int i=0;i<8;i++){ e[i]=__expf(x[i]-m); sum+=e[i]; }
#pragma unroll
    for (int o=16;o;o>>=1) sum += __shfl_xor_sync(~0u, sum, o);
    if (lid==0) red[wid]=sum;
    __syncthreads();
    sum = red[0];
#pragma unroll
    for (int i=1;i<8;i++) sum += red[i];
    float inv = 1.f/sum;
    __align__(16) bf16 hh[8], ll[8];
#pragma unroll
    for (int i=0;i<8;i++) split1(e[i]*inv, hh[i], ll[i]);
    *(uint4*)(Ph + row*NSEQ + tid*8) = *(uint4*)hh;
    *(uint4*)(Pl + row*NSEQ + tid*8) = *(uint4*)ll;
}

extern "C" void kernel_launch(void* const* d_in, const int* in_sizes, int n_in,
                              void* d_out, int out_size){
    const float* x     = (const float*)d_in[0];
    const float* w_qkv = (const float*)d_in[1];
    const float* w_out = (const float*)d_in[2];
    const float* b_out = (const float*)d_in[3];
    float* out = (float*)d_out;

    float *qkv, *att, *S; bf16 *Ph,*Pl,*xh,*xl,*wqh,*wql,*woh,*wol,*qh,*ql,*kh,*kl,*vth,*vtl,*ah,*al;
    cudaGetSymbolAddress((void**)&qkv,g_qkv); cudaGetSymbolAddress((void**)&att,g_att);
    cudaGetSymbolAddress((void**)&S,g_S);
    cudaGetSymbolAddress((void**)&Ph,g_Ph); cudaGetSymbolAddress((void**)&Pl,g_Pl);
    cudaGetSymbolAddress((void**)&xh,g_xh); cudaGetSymbolAddress((void**)&xl,g_xl);
    cudaGetSymbolAddress((void**)&wqh,g_wqh); cudaGetSymbolAddress((void**)&wql,g_wql);
    cudaGetSymbolAddress((void**)&woh,g_woh); cudaGetSymbolAddress((void**)&wol,g_wol);
    cudaGetSymbolAddress((void**)&qh,g_qh); cudaGetSymbolAddress((void**)&ql,g_ql);
    cudaGetSymbolAddress((void**)&kh,g_kh); cudaGetSymbolAddress((void**)&kl,g_kl);
    cudaGetSymbolAddress((void**)&vth,g_vth); cudaGetSymbolAddress((void**)&vtl,g_vtl);
    cudaGetSymbolAddress((void**)&ah,g_ah); cudaGetSymbolAddress((void**)&al,g_al);

    // splits of inputs
    split_arr<<<8192*1024/4/256,256>>>(x, xh, xl, 8192*1024/4);
    split_arr<<<3072*1024/4/256,256>>>(w_qkv, wqh, wql, 3072*1024/4);
    split_arr<<<1024*1024/4/256,256>>>(w_out, woh, wol, 1024*1024/4);

    // 1) qkv = x @ w_qkv^T : [8192, 3072]
    gemm3t<128><<<dim3(24,64,1),256>>>(xh,xl,wqh,wql,qkv,nullptr,1024,3072,0,0,0,0);

    // 2) per-head extract + split (Q pre-scaled, V transposed)
    qkv_split<<<32768,256>>>(qkv, qh,ql, kh,kl, vth,vtl);

    // 3) S = Q K^T : [64][2048, 2048]
    gemm3t<128><<<dim3(16,16,64),256>>>(qh,ql,kh,kl,S,nullptr,64,2048,
        (size_t)NSEQ*HD,(size_t)NSEQ*HD,(size_t)16*NSEQ*NSEQ,(size_t)NSEQ*NSEQ);

    // 4) softmax rows -> P hi/lo
    softmax_rows<<<dim3(2048,64),256>>>(S, Ph, Pl);

    // 5) att = P @ V (B rows = V^T) -> att[b][n][h*64+d]
    gemm3t<64><<<dim3(1,16,64),256>>>(Ph,Pl,vth,vtl,att,nullptr,2048,1024,
        (size_t)NSEQ*NSEQ,(size_t)HD*NSEQ,(size_t)NSEQ*DIMM,(size_t)HD);

    // 6) out = att @ w_out^T + b_out
    split_arr<<<8192*1024/4/256,256>>>(att, ah, al, 8192*1024/4);
    gemm3t<128><<<dim3(8,64,1),256>>>(ah,al,woh,wol,out,b_out,1024,1024,0,0,0,0);
}

// round 5
// speedup vs baseline: 5.2818x; 1.4724x over previous
#include <cuda_runtime.h>
#include <cuda_bf16.h>
#include <cstdint>
#include <cstddef>

#define DIMM 1024
#define NSEQ 2048
#define NB   4
#define NH   16
#define HD   64
#define NBH  (NB*NH)
#define ATTN_SCALE 0.03125f
#define BK 32

typedef __nv_bfloat16 bf16;

__device__ float g_qkv[(size_t)NB*NSEQ*3*DIMM];
__device__ bf16 g_xh[(size_t)NB*NSEQ*DIMM],  g_xl[(size_t)NB*NSEQ*DIMM];
__device__ bf16 g_wqh[(size_t)3*DIMM*DIMM],  g_wql[(size_t)3*DIMM*DIMM];
__device__ bf16 g_woh[(size_t)DIMM*DIMM],    g_wol[(size_t)DIMM*DIMM];
__device__ bf16 g_qh[(size_t)NBH*NSEQ*HD],   g_ql[(size_t)NBH*NSEQ*HD];
__device__ bf16 g_kh[(size_t)NBH*NSEQ*HD],   g_kl[(size_t)NBH*NSEQ*HD];
__device__ bf16 g_vth[(size_t)NBH*HD*NSEQ],  g_vtl[(size_t)NBH*HD*NSEQ];
__device__ bf16 g_ah[(size_t)NB*NSEQ*DIMM],  g_al[(size_t)NB*NSEQ*DIMM];

__device__ __forceinline__ uint32_t s2u(const void* p){
    uint32_t a; asm("{ .reg .u64 t; cvta.to.shared.u64 t, %1; cvt.u32.u64 %0, t; }":"=r"(a):"l"(p)); return a;
}
__device__ __forceinline__ void cp16(uint32_t s, const void* g){
    asm volatile("cp.async.cg.shared.global [%0], [%1], 16;"::"r"(s),"l"(g));
}
#define CPC() asm volatile("cp.async.commit_group;":::"memory")
#define CPW(n) asm volatile("cp.async.wait_group %0;"::"n"(n):"memory")

__device__ __forceinline__ void ldm4(uint32_t* f, uint32_t a){
    asm volatile("ldmatrix.sync.aligned.m8n8.x4.shared.b16 {%0,%1,%2,%3}, [%4];"
        :"=r"(f[0]),"=r"(f[1]),"=r"(f[2]),"=r"(f[3]):"r"(a));
}
__device__ __forceinline__ void mma16816(float* d, const uint32_t* a, uint32_t b0, uint32_t b1){
    asm volatile("mma.sync.aligned.m16n8k16.row.col.f32.bf16.bf16.f32 "
        "{%0,%1,%2,%3}, {%4,%5,%6,%7}, {%8,%9}, {%0,%1,%2,%3};"
        :"+f"(d[0]),"+f"(d[1]),"+f"(d[2]),"+f"(d[3])
        :"r"(a[0]),"r"(a[1]),"r"(a[2]),"r"(a[3]),"r"(b0),"r"(b1));
}
__device__ __forceinline__ void split1(float v, bf16& h, bf16& l){
    h = __float2bfloat16(v); l = __float2bfloat16(v - __bfloat162float(h));
}
__device__ __forceinline__ void split2(float a, float b, uint32_t& H, uint32_t& L){
    bf16 ha, la, hb, lb; split1(a,ha,la); split1(b,hb,lb);
    H = ((uint32_t)(*(uint16_t*)&hb) << 16) | (*(uint16_t*)&ha);
    L = ((uint32_t)(*(uint16_t*)&lb) << 16) | (*(uint16_t*)&la);
}

// ---------------- projection GEMM (unchanged from R4) ----------------
template<int BN>
__global__ __launch_bounds__(256, 2)
void gemm3t(const bf16* __restrict__ Ah, const bf16* __restrict__ Al,
            const bf16* __restrict__ Bh, const bf16* __restrict__ Bl,
            float* __restrict__ C, const float* __restrict__ bias,
            int K, int ldc, size_t sAz, size_t sBz, size_t sCz1, size_t sCz2){
    constexpr int NT = (BN==128) ? 8 : 4;
    constexpr int WNS = NT*8;
    constexpr int STAGE = (128+BN)*BK*2;
    __shared__ __align__(256) char smem[2*STAGE];

    const int tid = threadIdx.x, lane = tid&31, warp = tid>>5;
    const int wm = warp&3, wn = warp>>2;
    const int bn0 = blockIdx.x*BN, bm0 = blockIdx.y*128, z = blockIdx.z;
    const size_t lda = (size_t)K*2;

    const char* A0 = (const char*)(Ah + (size_t)z*sAz + (size_t)bm0*K);
    const char* A1 = (const char*)(Al + (size_t)z*sAz + (size_t)bm0*K);
    const char* B0 = (const char*)(Bh + (size_t)z*sBz + (size_t)bn0*K);
    const char* B1 = (const char*)(Bl + (size_t)z*sBz + (size_t)bn0*K);
    const int CK = K/BK, T = 3*CK;

    float acc[2][NT][4];
#pragma unroll
    for (int i=0;i<2;i++)
#pragma unroll
        for (int j=0;j<NT;j++)
#pragma unroll
            for (int k=0;k<4;k++) acc[i][j][k] = 0.f;

    auto load = [&](int t, int s){
        const int seg = t/CK, kk = t - seg*CK;
        const char* Ab = ((seg==1)?A1:A0) + (size_t)kk*64;
        const char* Bb = ((seg==2)?B1:B0) + (size_t)kk*64;
        const uint32_t ua = s2u(smem) + s*STAGE;
        const uint32_t ub = ua + 128*BK*2;
#pragma unroll
        for (int i=0;i<2;i++){ int id=tid+i*256, r=id>>2, c=id&3;
            cp16(ua + r*64 + ((c^((r>>1)&3))<<4), Ab + (size_t)r*lda + c*16); }
#pragma unroll
        for (int i=0;i<BN/64;i++){ int id=tid+i*256, r=id>>2, c=id&3;
            cp16(ub + r*64 + ((c^((r>>1)&3))<<4), Bb + (size_t)r*lda + c*16); }
    };

    load(0,0); CPC();
    for (int t=0; t<T; t++){
        const int s = t&1;
        if (t+1<T){ load(t+1, s^1); CPC(); CPW(1); } else { CPW(0); }
        __syncthreads();
        const uint32_t ua = s2u(smem) + s*STAGE;
        const uint32_t ub = ua + 128*BK*2;
        const int q = lane>>3, sub = lane&7;
#pragma unroll
        for (int ks=0; ks<2; ks++){
            uint32_t af[2][4], bfr[NT/2][4];
            const int ch = ks*2 + (q>>1);
#pragma unroll
            for (int mt=0; mt<2; mt++){
                int r = wm*32 + mt*16 + (q&1)*8 + sub;
                ldm4(af[mt], ua + r*64 + ((ch^((r>>1)&3))<<4));
            }
#pragma unroll
            for (int np=0; np<NT/2; np++){
                int r = wn*WNS + np*16 + (q&1)*8 + sub;
                ldm4(bfr[np], ub + r*64 + ((ch^((r>>1)&3))<<4));
            }
#pragma unroll
            for (int mt=0; mt<2; mt++)
#pragma unroll
                for (int nt=0; nt<NT; nt++)
                    mma16816(acc[mt][nt], af[mt], bfr[nt>>1][nt&1], bfr[nt>>1][2+(nt&1)]);
        }
        __syncthreads();
    }

    float* Cb = C + (size_t)(z>>4)*sCz1 + (size_t)(z&15)*sCz2;
#pragma unroll
    for (int mt=0; mt<2; mt++){
        const int m0 = bm0 + wm*32 + mt*16 + (lane>>2);
#pragma unroll
        for (int nt=0; nt<NT; nt++){
            const int n = bn0 + wn*WNS + nt*8 + (lane&3)*2;
            float bx = 0.f, by = 0.f;
            if (bias){ bx = bias[n]; by = bias[n+1]; }
            float2 v0 = {acc[mt][nt][0]+bx, acc[mt][nt][1]+by};
            float2 v1 = {acc[mt][nt][2]+bx, acc[mt][nt][3]+by};
            *(float2*)(Cb + (size_t)m0*ldc + n) = v0;
            *(float2*)(Cb + (size_t)(m0+8)*ldc + n) = v1;
        }
    }
}

// ---------------- fused flash attention (mma.sync, split-bf16) ----------------
// grid (16 qtiles, 64 bh), 256 thr, 8 warps x 16 q-rows.
// smem: Qh(16K) Ql(16K), 2 stages x [Kh 16K | Kl 16K | Vh 16K | Vl 16K]
__global__ __launch_bounds__(256, 1)
void flash_mma(const bf16* __restrict__ qh, const bf16* __restrict__ ql,
               const bf16* __restrict__ kh, const bf16* __restrict__ kl,
               const bf16* __restrict__ vth, const bf16* __restrict__ vtl,
               bf16* __restrict__ oh, bf16* __restrict__ ol){
    extern __shared__ char sm[];
    const uint32_t su = s2u(sm);
    const uint32_t QHs = su, QLs = su + 16384, ST = su + 32768;
    const int tid = threadIdx.x, lane = tid&31, warp = tid>>5;
    const int q2 = lane>>3, sub = lane&7;
    const int qb = blockIdx.x, z = blockIdx.y;

    const char* Qhg = (const char*)(qh + ((size_t)z*NSEQ + (size_t)qb*128)*HD);
    const char* Qlg = (const char*)(ql + ((size_t)z*NSEQ + (size_t)qb*128)*HD);
    const char* Khg = (const char*)(kh + (size_t)z*NSEQ*HD);
    const char* Klg = (const char*)(kl + (size_t)z*NSEQ*HD);
    const char* Vhg = (const char*)(vth + (size_t)z*HD*NSEQ);
    const char* Vlg = (const char*)(vtl + (size_t)z*HD*NSEQ);

#pragma unroll
    for (int i=0;i<4;i++){ int id=tid+i*256, r=id>>3, c=id&7;
        uint32_t off = r*128 + ((c^(r&7))<<4);
        cp16(QHs+off, Qhg + (size_t)id*16);
        cp16(QLs+off, Qlg + (size_t)id*16); }
    CPC();

    auto loadkv = [&](int t, int s){
        uint32_t b = ST + s*65536;
#pragma unroll
        for (int i=0;i<4;i++){ int id=tid+i*256, r=id>>3, c=id&7;
            uint32_t off = r*128 + ((c^(r&7))<<4);
            size_t g = (size_t)t*16384 + (size_t)id*16;
            cp16(b+off, Khg+g); cp16(b+16384+off, Klg+g); }
#pragma unroll
        for (int i=0;i<4;i++){ int id=tid+i*256, r=id>>4, c=id&15;
            uint32_t off = r*256 + ((c>>3)<<7) + (((c&7)^(r&7))<<4);
            size_t g = (size_t)t*256 + (size_t)r*4096 + (size_t)c*16;
            cp16(b+32768+off, Vhg+g); cp16(b+49152+off, Vlg+g); }
    };
    loadkv(0,0); CPC();

    CPW(1); __syncthreads();          // Q resident
    uint32_t qhf[4][4], qlf[4][4];
    {
        uint32_t rb = (uint32_t)(warp*16 + (q2&1)*8 + sub)*128;
#pragma unroll
        for (int ks=0;ks<4;ks++){
            uint32_t co = (uint32_t)(((ks*2+(q2>>1))^sub)<<4);
            ldm4(qhf[ks], QHs + rb + co);
            ldm4(qlf[ks], QLs + rb + co);
        }
    }

    float m0=-1e30f, m1=-1e30f, l0=0.f, l1=0.f;
    float oacc[8][4];
#pragma unroll
    for (int i=0;i<8;i++){ oacc[i][0]=0.f; oacc[i][1]=0.f; oacc[i][2]=0.f; oacc[i][3]=0.f; }

    const uint32_t krb = (uint32_t)((q2&1)*8+sub)*128;
    const uint32_t vrb = (uint32_t)((q2&1)*8+sub)*256;

    for (int t=0;t<16;t++){
        const int s = t&1;
        if (t<15){ loadkv(t+1, s^1); CPC(); CPW(1); } else { CPW(0); }
        __syncthreads();
        const uint32_t kb = ST + s*65536;

        float sacc[16][4];
#pragma unroll
        for (int i=0;i<16;i++){ sacc[i][0]=0.f; sacc[i][1]=0.f; sacc[i][2]=0.f; sacc[i][3]=0.f; }

#pragma unroll
        for (int ks=0;ks<4;ks++){
            uint32_t bfr[8][4];
            const uint32_t co = (uint32_t)(((ks*2+(q2>>1))^sub)<<4);
#pragma unroll
            for (int g=0;g<8;g++) ldm4(bfr[g], kb + krb + g*2048 + co);
#pragma unroll
            for (int nt=0;nt<16;nt++) mma16816(sacc[nt], qhf[ks], bfr[nt>>1][nt&1], bfr[nt>>1][2+(nt&1)]);
#pragma unroll
            for (int nt=0;nt<16;nt++) mma16816(sacc[nt], qlf[ks], bfr[nt>>1][nt&1], bfr[nt>>1][2+(nt&1)]);
#pragma unroll
            for (int g=0;g<8;g++) ldm4(bfr[g], kb + 16384 + krb + g*2048 + co);
#pragma unroll
            for (int nt=0;nt<16;nt++) mma16816(sacc[nt], qhf[ks], bfr[nt>>1][nt&1], bfr[nt>>1][2+(nt&1)]);
        }

        // online softmax (rows: lane>>2 and +8)
        float mt0=-1e30f, mt1=-1e30f;
#pragma unroll
        for (int nt=0;nt<16;nt++){
            mt0 = fmaxf(mt0, fmaxf(sacc[nt][0], sacc[nt][1]));
            mt1 = fmaxf(mt1, fmaxf(sacc[nt][2], sacc[nt][3]));
        }
        mt0 = fmaxf(mt0, __shfl_xor_sync(~0u, mt0, 1));
        mt0 = fmaxf(mt0, __shfl_xor_sync(~0u, mt0, 2));
        mt1 = fmaxf(mt1, __shfl_xor_sync(~0u, mt1, 1));
        mt1 = fmaxf(mt1, __shfl_xor_sync(~0u, mt1, 2));
        float nm0 = fmaxf(m0, mt0), nm1 = fmaxf(m1, mt1);
        float a0 = __expf(m0-nm0), a1 = __expf(m1-nm1);
        m0 = nm0; m1 = nm1;
        float s0=0.f, s1=0.f;
#pragma unroll
        for (int nt=0;nt<16;nt++){
            sacc[nt][0]=__expf(sacc[nt][0]-nm0); s0+=sacc[nt][0];
            sacc[nt][1]=__expf(sacc[nt][1]-nm0); s0+=sacc[nt][1];
            sacc[nt][2]=__expf(sacc[nt][2]-nm1); s1+=sacc[nt][2];
            sacc[nt][3]=__expf(sacc[nt][3]-nm1); s1+=sacc[nt][3];
        }
        s0 += __shfl_xor_sync(~0u,s0,1); s0 += __shfl_xor_sync(~0u,s0,2);
        s1 += __shfl_xor_sync(~0u,s1,1); s1 += __shfl_xor_sync(~0u,s1,2);
        l0 = l0*a0 + s0; l1 = l1*a1 + s1;
#pragma unroll
        for (int nd=0;nd<8;nd++){ oacc[nd][0]*=a0; oacc[nd][1]*=a0; oacc[nd][2]*=a1; oacc[nd][3]*=a1; }

        // PV: O += (Ph+Pl) Vh + Ph Vl
        const uint32_t vb = kb + 32768;
#pragma unroll
        for (int j=0;j<8;j++){
            uint32_t pha[4], pla[4];
            split2(sacc[2*j][0],   sacc[2*j][1],   pha[0], pla[0]);
            split2(sacc[2*j][2],   sacc[2*j][3],   pha[1], pla[1]);
            split2(sacc[2*j+1][0], sacc[2*j+1][1], pha[2], pla[2]);
            split2(sacc[2*j+1][2], sacc[2*j+1][3], pha[3], pla[3]);
            const int ch = j*2 + (q2>>1);
            const uint32_t co = (uint32_t)(((ch>>3)<<7) + (((ch&7)^sub)<<4));
            uint32_t bv[4][4], bl[4][4];
#pragma unroll
            for (int g=0;g<4;g++){
                ldm4(bv[g], vb + vrb + g*4096 + co);
                ldm4(bl[g], vb + 16384 + vrb + g*4096 + co);
            }
#pragma unroll
            for (int nd=0;nd<8;nd++){
                mma16816(oacc[nd], pha, bv[nd>>1][nd&1], bv[nd>>1][2+(nd&1)]);
                mma16816(oacc[nd], pla, bv[nd>>1][nd&1], bv[nd>>1][2+(nd&1)]);
                mma16816(oacc[nd], pha, bl[nd>>1][nd&1], bl[nd>>1][2+(nd&1)]);
            }
        }
        __syncthreads();
    }

    // epilogue: O/l -> bf16 hi/lo directly
    const float i0 = 1.f/l0, i1 = 1.f/l1;
    const int r0 = warp*16 + (lane>>2);
    bf16* oph = oh + ((size_t)(z>>4)*NSEQ + (size_t)qb*128)*DIMM + (size_t)(z&15)*HD;
    bf16* opl = ol + ((size_t)(z>>4)*NSEQ + (size_t)qb*128)*DIMM + (size_t)(z&15)*HD;
#pragma unroll
    for (int nd=0;nd<8;nd++){
        const int d = nd*8 + (lane&3)*2;
        uint32_t H, L;
        split2(oacc[nd][0]*i0, oacc[nd][1]*i0, H, L);
        *(uint32_t*)(oph + (size_t)r0*DIMM + d) = H;
        *(uint32_t*)(opl + (size_t)r0*DIMM + d) = L;
        split2(oacc[nd][2]*i1, oacc[nd][3]*i1, H, L);
        *(uint32_t*)(oph + (size_t)(r0+8)*DIMM + d) = H;
        *(uint32_t*)(opl + (size_t)(r0+8)*DIMM + d) = L;
    }
}

// ---------------- helpers ----------------
__global__ void split_arr(const float* __restrict__ in, bf16* __restrict__ h, bf16* __restrict__ l, int n4){
    int i = blockIdx.x*blockDim.x + threadIdx.x;
    if (i>=n4) return;
    float4 v = ((const float4*)in)[i];
    __align__(8) bf16 hh[4], ll[4];
    split1(v.x,hh[0],ll[0]); split1(v.y,hh[1],ll[1]); split1(v.z,hh[2],ll[2]); split1(v.w,hh[3],ll[3]);
    ((uint2*)h)[i] = *(uint2*)hh; ((uint2*)l)[i] = *(uint2*)ll;
}

__global__ void qkv_split(const float* __restrict__ qkv,
        bf16* __restrict__ qh, bf16* __restrict__ ql, bf16* __restrict__ kh, bf16* __restrict__ kl,
        bf16* __restrict__ vth, bf16* __restrict__ vtl){
    int idx = blockIdx.x*blockDim.x + threadIdx.x;
    int d = idx&63, h = (idx>>6)&15, n = (idx>>10)&2047, b = idx>>21;
    size_t base = ((size_t)(b*NSEQ+n))*(3*DIMM) + h*HD + d;
    size_t qi = (((size_t)(b*NH+h))*NSEQ + n)*HD + d;
    size_t vi = (((size_t)(b*NH+h))*HD + d)*NSEQ + n;
    split1(qkv[base]*ATTN_SCALE, qh[qi], ql[qi]);
    split1(qkv[base+DIMM], kh[qi], kl[qi]);
    split1(qkv[base+2*DIMM], vth[vi], vtl[vi]);
}

extern "C" void kernel_launch(void* const* d_in, const int* in_sizes, int n_in,
                              void* d_out, int out_size){
    const float* x     = (const float*)d_in[0];
    const float* w_qkv = (const float*)d_in[1];
    const float* w_out = (const float*)d_in[2];
    const float* b_out = (const float*)d_in[3];
    float* out = (float*)d_out;

    float *qkv; bf16 *xh,*xl,*wqh,*wql,*woh,*wol,*qh,*ql,*kh,*kl,*vth,*vtl,*ah,*al;
    cudaGetSymbolAddress((void**)&qkv,g_qkv);
    cudaGetSymbolAddress((void**)&xh,g_xh); cudaGetSymbolAddress((void**)&xl,g_xl);
    cudaGetSymbolAddress((void**)&wqh,g_wqh); cudaGetSymbolAddress((void**)&wql,g_wql);
    cudaGetSymbolAddress((void**)&woh,g_woh); cudaGetSymbolAddress((void**)&wol,g_wol);
    cudaGetSymbolAddress((void**)&qh,g_qh); cudaGetSymbolAddress((void**)&ql,g_ql);
    cudaGetSymbolAddress((void**)&kh,g_kh); cudaGetSymbolAddress((void**)&kl,g_kl);
    cudaGetSymbolAddress((void**)&vth,g_vth); cudaGetSymbolAddress((void**)&vtl,g_vtl);
    cudaGetSymbolAddress((void**)&ah,g_ah); cudaGetSymbolAddress((void**)&al,g_al);

    cudaFuncSetAttribute(flash_mma, cudaFuncAttributeMaxDynamicSharedMemorySize, 163840);

    // splits of inputs
    split_arr<<<8192*1024/4/256,256>>>(x, xh, xl, 8192*1024/4);
    split_arr<<<3072*1024/4/256,256>>>(w_qkv, wqh, wql, 3072*1024/4);
    split_arr<<<1024*1024/4/256,256>>>(w_out, woh, wol, 1024*1024/4);

    // 1) qkv = x @ w_qkv^T : [8192, 3072]
    gemm3t<128><<<dim3(24,64,1),256>>>(xh,xl,wqh,wql,qkv,nullptr,1024,3072,0,0,0,0);

    // 2) per-head extract + split (Q pre-scaled, V transposed)
    qkv_split<<<32768,256>>>(qkv, qh,ql, kh,kl, vth,vtl);

    // 3) fused flash attention -> ah/al (bf16 hi/lo of attention output)
    flash_mma<<<dim3(16,64),256,163840>>>(qh,ql,kh,kl,vth,vtl,ah,al);

    // 4) out = att @ w_out^T + b_out
    gemm3t<128><<<dim3(8,64,1),256>>>(ah,al,woh,wol,out,b_out,1024,1024,0,0,0,0);
}

// round 6
// speedup vs baseline: 5.6217x; 1.0643x over previous
#include <cuda_runtime.h>
#include <cuda_bf16.h>
#include <cstdint>
#include <cstddef>

#define DIMM 1024
#define NSEQ 2048
#define NB   4
#define NH   16
#define HD   64
#define NBH  (NB*NH)
#define ATTN_SCALE 0.03125f
#define BK 32

typedef __nv_bfloat16 bf16;

__device__ float g_qkv[(size_t)NB*NSEQ*3*DIMM];
__device__ bf16 g_xh[(size_t)NB*NSEQ*DIMM],  g_xl[(size_t)NB*NSEQ*DIMM];
__device__ bf16 g_wqh[(size_t)3*DIMM*DIMM],  g_wql[(size_t)3*DIMM*DIMM];
__device__ bf16 g_woh[(size_t)DIMM*DIMM],    g_wol[(size_t)DIMM*DIMM];
__device__ bf16 g_qh[(size_t)NBH*NSEQ*HD],   g_ql[(size_t)NBH*NSEQ*HD];
__device__ bf16 g_kh[(size_t)NBH*NSEQ*HD],   g_kl[(size_t)NBH*NSEQ*HD];
__device__ bf16 g_vth[(size_t)NBH*HD*NSEQ],  g_vtl[(size_t)NBH*HD*NSEQ];
__device__ bf16 g_ah[(size_t)NB*NSEQ*DIMM],  g_al[(size_t)NB*NSEQ*DIMM];

__device__ __forceinline__ uint32_t s2u(const void* p){
    uint32_t a; asm("{ .reg .u64 t; cvta.to.shared.u64 t, %1; cvt.u32.u64 %0, t; }":"=r"(a):"l"(p)); return a;
}
__device__ __forceinline__ void cp16(uint32_t s, const void* g){
    asm volatile("cp.async.cg.shared.global [%0], [%1], 16;"::"r"(s),"l"(g));
}
#define CPC() asm volatile("cp.async.commit_group;":::"memory")
#define CPW(n) asm volatile("cp.async.wait_group %0;"::"n"(n):"memory")

__device__ __forceinline__ void ldm4(uint32_t* f, uint32_t a){
    asm volatile("ldmatrix.sync.aligned.m8n8.x4.shared.b16 {%0,%1,%2,%3}, [%4];"
        :"=r"(f[0]),"=r"(f[1]),"=r"(f[2]),"=r"(f[3]):"r"(a));
}
__device__ __forceinline__ void mma16816(float* d, const uint32_t* a, uint32_t b0, uint32_t b1){
    asm volatile("mma.sync.aligned.m16n8k16.row.col.f32.bf16.bf16.f32 "
        "{%0,%1,%2,%3}, {%4,%5,%6,%7}, {%8,%9}, {%0,%1,%2,%3};"
        :"+f"(d[0]),"+f"(d[1]),"+f"(d[2]),"+f"(d[3])
        :"r"(a[0]),"r"(a[1]),"r"(a[2]),"r"(a[3]),"r"(b0),"r"(b1));
}
__device__ __forceinline__ void split1(float v, bf16& h, bf16& l){
    h = __float2bfloat16(v); l = __float2bfloat16(v - __bfloat162float(h));
}
__device__ __forceinline__ void split2(float a, float b, uint32_t& H, uint32_t& L){
    bf16 ha, la, hb, lb; split1(a,ha,la); split1(b,hb,lb);
    H = ((uint32_t)(*(uint16_t*)&hb) << 16) | (*(uint16_t*)&ha);
    L = ((uint32_t)(*(uint16_t*)&lb) << 16) | (*(uint16_t*)&la);
}

// ---------------- fused 3-term projection GEMM ----------------
// C[m][n] = (Ah+Al)[m,:].(Bh+Bl)[n,:] via Ah.Bh + Al.Bh + Ah.Bl, all terms
// computed per K-chunk with operands loaded ONCE. 128x128 tile, BK=32.
// stage layout (32KB): Ah[8K] Al[8K] Bh[8K] Bl[8K]
__global__ __launch_bounds__(256, 2)
void gemm3f(const bf16* __restrict__ Ah, const bf16* __restrict__ Al,
            const bf16* __restrict__ Bh, const bf16* __restrict__ Bl,
            float* __restrict__ C, const float* __restrict__ bias,
            int K, int ldc){
    constexpr int STAGE = 32768;
    extern __shared__ __align__(256) char smem[];
    const uint32_t su = s2u(smem);

    const int tid = threadIdx.x, lane = tid&31, warp = tid>>5;
    const int wm = warp&3, wn = warp>>2;
    const int bn0 = blockIdx.x*128, bm0 = blockIdx.y*128;
    const size_t lda = (size_t)K*2;

    const char* A0 = (const char*)(Ah + (size_t)bm0*K);
    const char* A1 = (const char*)(Al + (size_t)bm0*K);
    const char* B0 = (const char*)(Bh + (size_t)bn0*K);
    const char* B1 = (const char*)(Bl + (size_t)bn0*K);
    const int CK = K/BK;

    float acc[2][8][4];
#pragma unroll
    for (int i=0;i<2;i++)
#pragma unroll
        for (int j=0;j<8;j++)
#pragma unroll
            for (int k=0;k<4;k++) acc[i][j][k] = 0.f;

    auto load = [&](int t, int s){
        const uint32_t u = su + s*STAGE;
        const size_t ko = (size_t)t*64;
#pragma unroll
        for (int i=0;i<2;i++){ int id=tid+i*256, r=id>>2, c=id&3;
            uint32_t off = r*64 + ((c^((r>>1)&3))<<4);
            size_t g = (size_t)r*lda + c*16 + ko;
            cp16(u + off,        A0 + g);
            cp16(u + 8192 + off, A1 + g);
            cp16(u + 16384 + off, B0 + g);
            cp16(u + 24576 + off, B1 + g); }
    };

    load(0,0); CPC();
    for (int t=0; t<CK; t++){
        const int s = t&1;
        if (t+1<CK){ load(t+1, s^1); CPC(); CPW(1); } else { CPW(0); }
        __syncthreads();
        const uint32_t u = su + s*STAGE;
        const int q = lane>>3, sub = lane&7;
#pragma unroll
        for (int ks=0; ks<2; ks++){
            uint32_t afh[2][4], afl[2][4];
            const int ch = ks*2 + (q>>1);
#pragma unroll
            for (int mt=0; mt<2; mt++){
                int r = wm*32 + mt*16 + (q&1)*8 + sub;
                uint32_t off = r*64 + ((ch^((r>>1)&3))<<4);
                ldm4(afh[mt], u + off);
                ldm4(afl[mt], u + 8192 + off);
            }
#pragma unroll
            for (int np=0; np<4; np++){
                int r = wn*64 + np*16 + (q&1)*8 + sub;
                uint32_t off = r*64 + ((ch^((r>>1)&3))<<4);
                uint32_t bfh[4], bfl[4];
                ldm4(bfh, u + 16384 + off);
                ldm4(bfl, u + 24576 + off);
#pragma unroll
                for (int nn=0; nn<2; nn++){
                    const int nt = 2*np + nn;
#pragma unroll
                    for (int mt=0; mt<2; mt++){
                        mma16816(acc[mt][nt], afh[mt], bfh[nn], bfh[2+nn]);
                        mma16816(acc[mt][nt], afl[mt], bfh[nn], bfh[2+nn]);
                        mma16816(acc[mt][nt], afh[mt], bfl[nn], bfl[2+nn]);
                    }
                }
            }
        }
        __syncthreads();
    }

#pragma unroll
    for (int mt=0; mt<2; mt++){
        const int m0 = bm0 + wm*32 + mt*16 + (lane>>2);
#pragma unroll
        for (int nt=0; nt<8; nt++){
            const int n = bn0 + wn*64 + nt*8 + (lane&3)*2;
            float bx = 0.f, by = 0.f;
            if (bias){ bx = bias[n]; by = bias[n+1]; }
            float2 v0 = {acc[mt][nt][0]+bx, acc[mt][nt][1]+by};
            float2 v1 = {acc[mt][nt][2]+bx, acc[mt][nt][3]+by};
            *(float2*)(C + (size_t)m0*ldc + n) = v0;
            *(float2*)(C + (size_t)(m0+8)*ldc + n) = v1;
        }
    }
}

// ---------------- fused flash attention (unchanged from R5) ----------------
__global__ __launch_bounds__(256, 1)
void flash_mma(const bf16* __restrict__ qh, const bf16* __restrict__ ql,
               const bf16* __restrict__ kh, const bf16* __restrict__ kl,
               const bf16* __restrict__ vth, const bf16* __restrict__ vtl,
               bf16* __restrict__ oh, bf16* __restrict__ ol){
    extern __shared__ char sm[];
    const uint32_t su = s2u(sm);
    const uint32_t QHs = su, QLs = su + 16384, ST = su + 32768;
    const int tid = threadIdx.x, lane = tid&31, warp = tid>>5;
    const int q2 = lane>>3, sub = lane&7;
    const int qb = blockIdx.x, z = blockIdx.y;

    const char* Qhg = (const char*)(qh + ((size_t)z*NSEQ + (size_t)qb*128)*HD);
    const char* Qlg = (const char*)(ql + ((size_t)z*NSEQ + (size_t)qb*128)*HD);
    const char* Khg = (const char*)(kh + (size_t)z*NSEQ*HD);
    const char* Klg = (const char*)(kl + (size_t)z*NSEQ*HD);
    const char* Vhg = (const char*)(vth + (size_t)z*HD*NSEQ);
    const char* Vlg = (const char*)(vtl + (size_t)z*HD*NSEQ);

#pragma unroll
    for (int i=0;i<4;i++){ int id=tid+i*256, r=id>>3, c=id&7;
        uint32_t off = r*128 + ((c^(r&7))<<4);
        cp16(QHs+off, Qhg + (size_t)id*16);
        cp16(QLs+off, Qlg + (size_t)id*16); }
    CPC();

    auto loadkv = [&](int t, int s){
        uint32_t b = ST + s*65536;
#pragma unroll
        for (int i=0;i<4;i++){ int id=tid+i*256, r=id>>3, c=id&7;
            uint32_t off = r*128 + ((c^(r&7))<<4);
            size_t g = (size_t)t*16384 + (size_t)id*16;
            cp16(b+off, Khg+g); cp16(b+16384+off, Klg+g); }
#pragma unroll
        for (int i=0;i<4;i++){ int id=tid+i*256, r=id>>4, c=id&15;
            uint32_t off = r*256 + ((c>>3)<<7) + (((c&7)^(r&7))<<4);
            size_t g = (size_t)t*256 + (size_t)r*4096 + (size_t)c*16;
            cp16(b+32768+off, Vhg+g); cp16(b+49152+off, Vlg+g); }
    };
    loadkv(0,0); CPC();

    CPW(1); __syncthreads();
    uint32_t qhf[4][4], qlf[4][4];
    {
        uint32_t rb = (uint32_t)(warp*16 + (q2&1)*8 + sub)*128;
#pragma unroll
        for (int ks=0;ks<4;ks++){
            uint32_t co = (uint32_t)(((ks*2+(q2>>1))^sub)<<4);
            ldm4(qhf[ks], QHs + rb + co);
            ldm4(qlf[ks], QLs + rb + co);
        }
    }

    float m0=-1e30f, m1=-1e30f, l0=0.f, l1=0.f;
    float oacc[8][4];
#pragma unroll
    for (int i=0;i<8;i++){ oacc[i][0]=0.f; oacc[i][1]=0.f; oacc[i][2]=0.f; oacc[i][3]=0.f; }

    const uint32_t krb = (uint32_t)((q2&1)*8+sub)*128;
    const uint32_t vrb = (uint32_t)((q2&1)*8+sub)*256;

    for (int t=0;t<16;t++){
        const int s = t&1;
        if (t<15){ loadkv(t+1, s^1); CPC(); CPW(1); } else { CPW(0); }
        __syncthreads();
        const uint32_t kb = ST + s*65536;

        float sacc[16][4];
#pragma unroll
        for (int i=0;i<16;i++){ sacc[i][0]=0.f; sacc[i][1]=0.f; sacc[i][2]=0.f; sacc[i][3]=0.f; }

#pragma unroll
        for (int ks=0;ks<4;ks++){
            uint32_t bfr[8][4];
            const uint32_t co = (uint32_t)(((ks*2+(q2>>1))^sub)<<4);
#pragma unroll
            for (int g=0;g<8;g++) ldm4(bfr[g], kb + krb + g*2048 + co);
#pragma unroll
            for (int nt=0;nt<16;nt++) mma16816(sacc[nt], qhf[ks], bfr[nt>>1][nt&1], bfr[nt>>1][2+(nt&1)]);
#pragma unroll
            for (int nt=0;nt<16;nt++) mma16816(sacc[nt], qlf[ks], bfr[nt>>1][nt&1], bfr[nt>>1][2+(nt&1)]);
#pragma unroll
            for (int g=0;g<8;g++) ldm4(bfr[g], kb + 16384 + krb + g*2048 + co);
#pragma unroll
            for (int nt=0;nt<16;nt++) mma16816(sacc[nt], qhf[ks], bfr[nt>>1][nt&1], bfr[nt>>1][2+(nt&1)]);
        }

        float mt0=-1e30f, mt1=-1e30f;
#pragma unroll
        for (int nt=0;nt<16;nt++){
            mt0 = fmaxf(mt0, fmaxf(sacc[nt][0], sacc[nt][1]));
            mt1 = fmaxf(mt1, fmaxf(sacc[nt][2], sacc[nt][3]));
        }
        mt0 = fmaxf(mt0, __shfl_xor_sync(~0u, mt0, 1));
        mt0 = fmaxf(mt0, __shfl_xor_sync(~0u, mt0, 2));
        mt1 = fmaxf(mt1, __shfl_xor_sync(~0u, mt1, 1));
        mt1 = fmaxf(mt1, __shfl_xor_sync(~0u, mt1, 2));
        float nm0 = fmaxf(m0, mt0), nm1 = fmaxf(m1, mt1);
        float a0 = __expf(m0-nm0), a1 = __expf(m1-nm1);
        m0 = nm0; m1 = nm1;
        float s0=0.f, s1=0.f;
#pragma unroll
        for (int nt=0;nt<16;nt++){
            sacc[nt][0]=__expf(sacc[nt][0]-nm0); s0+=sacc[nt][0];
            sacc[nt][1]=__expf(sacc[nt][1]-nm0); s0+=sacc[nt][1];
            sacc[nt][2]=__expf(sacc[nt][2]-nm1); s1+=sacc[nt][2];
            sacc[nt][3]=__expf(sacc[nt][3]-nm1); s1+=sacc[nt][3];
        }
        s0 += __shfl_xor_sync(~0u,s0,1); s0 += __shfl_xor_sync(~0u,s0,2);
        s1 += __shfl_xor_sync(~0u,s1,1); s1 += __shfl_xor_sync(~0u,s1,2);
        l0 = l0*a0 + s0; l1 = l1*a1 + s1;
#pragma unroll
        for (int nd=0;nd<8;nd++){ oacc[nd][0]*=a0; oacc[nd][1]*=a0; oacc[nd][2]*=a1; oacc[nd][3]*=a1; }

        const uint32_t vb = kb + 32768;
#pragma unroll
        for (int j=0;j<8;j++){
            uint32_t pha[4], pla[4];
            split2(sacc[2*j][0],   sacc[2*j][1],   pha[0], pla[0]);
            split2(sacc[2*j][2],   sacc[2*j][3],   pha[1], pla[1]);
            split2(sacc[2*j+1][0], sacc[2*j+1][1], pha[2], pla[2]);
            split2(sacc[2*j+1][2], sacc[2*j+1][3], pha[3], pla[3]);
            const int ch = j*2 + (q2>>1);
            const uint32_t co = (uint32_t)(((ch>>3)<<7) + (((ch&7)^sub)<<4));
            uint32_t bv[4][4], bl[4][4];
#pragma unroll
            for (int g=0;g<4;g++){
                ldm4(bv[g], vb + vrb + g*4096 + co);
                ldm4(bl[g], vb + 16384 + vrb + g*4096 + co);
            }
#pragma unroll
            for (int nd=0;nd<8;nd++){
                mma16816(oacc[nd], pha, bv[nd>>1][nd&1], bv[nd>>1][2+(nd&1)]);
                mma16816(oacc[nd], pla, bv[nd>>1][nd&1], bv[nd>>1][2+(nd&1)]);
                mma16816(oacc[nd], pha, bl[nd>>1][nd&1], bl[nd>>1][2+(nd&1)]);
            }
        }
        __syncthreads();
    }

    const float i0 = 1.f/l0, i1 = 1.f/l1;
    const int r0 = warp*16 + (lane>>2);
    bf16* oph = oh + ((size_t)(z>>4)*NSEQ + (size_t)qb*128)*DIMM + (size_t)(z&15)*HD;
    bf16* opl = ol + ((size_t)(z>>4)*NSEQ + (size_t)qb*128)*DIMM + (size_t)(z&15)*HD;
#pragma unroll
    for (int nd=0;nd<8;nd++){
        const int d = nd*8 + (lane&3)*2;
        uint32_t H, L;
        split2(oacc[nd][0]*i0, oacc[nd][1]*i0, H, L);
        *(uint32_t*)(oph + (size_t)r0*DIMM + d) = H;
        *(uint32_t*)(opl + (size_t)r0*DIMM + d) = L;
        split2(oacc[nd][2]*i1, oacc[nd][3]*i1, H, L);
        *(uint32_t*)(oph + (size_t)(r0+8)*DIMM + d) = H;
        *(uint32_t*)(opl + (size_t)(r0+8)*DIMM + d) = L;
    }
}

// ---------------- helpers ----------------
__global__ void split_arr(const float* __restrict__ in, bf16* __restrict__ h, bf16* __restrict__ l, int n4){
    int i = blockIdx.x*blockDim.x + threadIdx.x;
    if (i>=n4) return;
    float4 v = ((const float4*)in)[i];
    __align__(8) bf16 hh[4], ll[4];
    split1(v.x,hh[0],ll[0]); split1(v.y,hh[1],ll[1]); split1(v.z,hh[2],ll[2]); split1(v.w,hh[3],ll[3]);
    ((uint2*)h)[i] = *(uint2*)hh; ((uint2*)l)[i] = *(uint2*)ll;
}

__global__ void qkv_split(const float* __restrict__ qkv,
        bf16* __restrict__ qh, bf16* __restrict__ ql, bf16* __restrict__ kh, bf16* __restrict__ kl,
        bf16* __restrict__ vth, bf16* __restrict__ vtl){
    int idx = blockIdx.x*blockDim.x + threadIdx.x;
    int d = idx&63, h = (idx>>6)&15, n = (idx>>10)&2047, b = idx>>21;
    size_t base = ((size_t)(b*NSEQ+n))*(3*DIMM) + h*HD + d;
    size_t qi = (((size_t)(b*NH+h))*NSEQ + n)*HD + d;
    size_t vi = (((size_t)(b*NH+h))*HD + d)*NSEQ + n;
    split1(qkv[base]*ATTN_SCALE, qh[qi], ql[qi]);
    split1(qkv[base+DIMM], kh[qi], kl[qi]);
    split1(qkv[base+2*DIMM], vth[vi], vtl[vi]);
}

extern "C" void kernel_launch(void* const* d_in, const int* in_sizes, int n_in,
                              void* d_out, int out_size){
    const float* x     = (const float*)d_in[0];
    const float* w_qkv = (const float*)d_in[1];
    const float* w_out = (const float*)d_in[2];
    const float* b_out = (const float*)d_in[3];
    float* out = (float*)d_out;

    float *qkv; bf16 *xh,*xl,*wqh,*wql,*woh,*wol,*qh,*ql,*kh,*kl,*vth,*vtl,*ah,*al;
    cudaGetSymbolAddress((void**)&qkv,g_qkv);
    cudaGetSymbolAddress((void**)&xh,g_xh); cudaGetSymbolAddress((void**)&xl,g_xl);
    cudaGetSymbolAddress((void**)&wqh,g_wqh); cudaGetSymbolAddress((void**)&wql,g_wql);
    cudaGetSymbolAddress((void**)&woh,g_woh); cudaGetSymbolAddress((void**)&wol,g_wol);
    cudaGetSymbolAddress((void**)&qh,g_qh); cudaGetSymbolAddress((void**)&ql,g_ql);
    cudaGetSymbolAddress((void**)&kh,g_kh); cudaGetSymbolAddress((void**)&kl,g_kl);
    cudaGetSymbolAddress((void**)&vth,g_vth); cudaGetSymbolAddress((void**)&vtl,g_vtl);
    cudaGetSymbolAddress((void**)&ah,g_ah); cudaGetSymbolAddress((void**)&al,g_al);

    cudaFuncSetAttribute(gemm3f, cudaFuncAttributeMaxDynamicSharedMemorySize, 65536);
    cudaFuncSetAttribute(flash_mma, cudaFuncAttributeMaxDynamicSharedMemorySize, 163840);

    split_arr<<<8192*1024/4/256,256>>>(x, xh, xl, 8192*1024/4);
    split_arr<<<3072*1024/4/256,256>>>(w_qkv, wqh, wql, 3072*1024/4);
    split_arr<<<1024*1024/4/256,256>>>(w_out, woh, wol, 1024*1024/4);

    // 1) qkv = x @ w_qkv^T : [8192, 3072]
    gemm3f<<<dim3(24,64),256,65536>>>(xh,xl,wqh,wql,qkv,nullptr,1024,3072);

    // 2) per-head extract + split (Q pre-scaled, V transposed)
    qkv_split<<<32768,256>>>(qkv, qh,ql, kh,kl, vth,vtl);

    // 3) fused flash attention -> ah/al
    flash_mma<<<dim3(16,64),256,163840>>>(qh,ql,kh,kl,vth,vtl,ah,al);

    // 4) out = att @ w_out^T + b_out
    gemm3f<<<dim3(8,64),256,65536>>>(ah,al,woh,wol,out,b_out,1024,1024);
}

// round 7
// speedup vs baseline: 6.5622x; 1.1673x over previous
#include <cuda_runtime.h>
#include <cuda_bf16.h>
#include <cstdint>
#include <cstddef>

#define DIMM 1024
#define NSEQ 2048
#define NB   4
#define NH   16
#define HD   64
#define NBH  (NB*NH)
#define ATTN_SCALE 0.03125f
#define BK 32

typedef __nv_bfloat16 bf16;

__device__ bf16 g_xh[(size_t)NB*NSEQ*DIMM],  g_xl[(size_t)NB*NSEQ*DIMM];
__device__ bf16 g_wqh[(size_t)3*DIMM*DIMM],  g_wql[(size_t)3*DIMM*DIMM];
__device__ bf16 g_woh[(size_t)DIMM*DIMM],    g_wol[(size_t)DIMM*DIMM];
__device__ bf16 g_qh[(size_t)NBH*NSEQ*HD],   g_ql[(size_t)NBH*NSEQ*HD];
__device__ bf16 g_kh[(size_t)NBH*NSEQ*HD],   g_kl[(size_t)NBH*NSEQ*HD];
__device__ bf16 g_vh[(size_t)NBH*NSEQ*HD],   g_vl[(size_t)NBH*NSEQ*HD];
__device__ bf16 g_ah[(size_t)NB*NSEQ*DIMM],  g_al[(size_t)NB*NSEQ*DIMM];

__device__ __forceinline__ uint32_t s2u(const void* p){
    uint32_t a; asm("{ .reg .u64 t; cvta.to.shared.u64 t, %1; cvt.u32.u64 %0, t; }":"=r"(a):"l"(p)); return a;
}
__device__ __forceinline__ void cp16(uint32_t s, const void* g){
    asm volatile("cp.async.cg.shared.global [%0], [%1], 16;"::"r"(s),"l"(g));
}
#define CPC() asm volatile("cp.async.commit_group;":::"memory")
#define CPW(n) asm volatile("cp.async.wait_group %0;"::"n"(n):"memory")

__device__ __forceinline__ void ldm4(uint32_t* f, uint32_t a){
    asm volatile("ldmatrix.sync.aligned.m8n8.x4.shared.b16 {%0,%1,%2,%3}, [%4];"
        :"=r"(f[0]),"=r"(f[1]),"=r"(f[2]),"=r"(f[3]):"r"(a));
}
__device__ __forceinline__ void ldm4t(uint32_t* f, uint32_t a){
    asm volatile("ldmatrix.sync.aligned.m8n8.x4.trans.shared.b16 {%0,%1,%2,%3}, [%4];"
        :"=r"(f[0]),"=r"(f[1]),"=r"(f[2]),"=r"(f[3]):"r"(a));
}
__device__ __forceinline__ void mma16816(float* d, const uint32_t* a, uint32_t b0, uint32_t b1){
    asm volatile("mma.sync.aligned.m16n8k16.row.col.f32.bf16.bf16.f32 "
        "{%0,%1,%2,%3}, {%4,%5,%6,%7}, {%8,%9}, {%0,%1,%2,%3};"
        :"+f"(d[0]),"+f"(d[1]),"+f"(d[2]),"+f"(d[3])
        :"r"(a[0]),"r"(a[1]),"r"(a[2]),"r"(a[3]),"r"(b0),"r"(b1));
}
__device__ __forceinline__ void split1(float v, bf16& h, bf16& l){
    h = __float2bfloat16(v); l = __float2bfloat16(v - __bfloat162float(h));
}
__device__ __forceinline__ void split2(float a, float b, uint32_t& H, uint32_t& L){
    bf16 ha, la, hb, lb; split1(a,ha,la); split1(b,hb,lb);
    H = ((uint32_t)(*(uint16_t*)&hb) << 16) | (*(uint16_t*)&ha);
    L = ((uint32_t)(*(uint16_t*)&lb) << 16) | (*(uint16_t*)&la);
}

// ---------------- fused 3-term projection GEMM, 3-stage pipeline ----------------
// C = (Ah+Al)(Bh+Bl)^T via Ah.Bh + Al.Bh + Ah.Bl. 128x128 tile, BK=32.
// MODE 0: write fp32 C (+bias).  MODE 1: write q/k/v per-head split-bf16 directly.
template<int MODE>
__global__ __launch_bounds__(256, 2)
void gemm3f(const bf16* __restrict__ Ah, const bf16* __restrict__ Al,
            const bf16* __restrict__ Bh, const bf16* __restrict__ Bl,
            float* __restrict__ C, const float* __restrict__ bias,
            bf16* __restrict__ qh, bf16* __restrict__ ql,
            bf16* __restrict__ kh, bf16* __restrict__ kl,
            bf16* __restrict__ vh, bf16* __restrict__ vl,
            int K, int ldc){
    constexpr int STAGE = 32768;
    extern __shared__ __align__(256) char smem[];
    const uint32_t su = s2u(smem);

    const int tid = threadIdx.x, lane = tid&31, warp = tid>>5;
    const int wm = warp&3, wn = warp>>2;
    const int bn0 = blockIdx.x*128, bm0 = blockIdx.y*128;
    const size_t lda = (size_t)K*2;

    const char* A0 = (const char*)(Ah + (size_t)bm0*K);
    const char* A1 = (const char*)(Al + (size_t)bm0*K);
    const char* B0 = (const char*)(Bh + (size_t)bn0*K);
    const char* B1 = (const char*)(Bl + (size_t)bn0*K);
    const int CK = K/BK;

    float acc[2][8][4];
#pragma unroll
    for (int i=0;i<2;i++)
#pragma unroll
        for (int j=0;j<8;j++)
#pragma unroll
            for (int k=0;k<4;k++) acc[i][j][k] = 0.f;

    auto load = [&](int t, int s){
        const uint32_t u = su + s*STAGE;
        const size_t ko = (size_t)t*64;
#pragma unroll
        for (int i=0;i<2;i++){ int id=tid+i*256, r=id>>2, c=id&3;
            uint32_t off = r*64 + ((c^((r>>1)&3))<<4);
            size_t g = (size_t)r*lda + c*16 + ko;
            cp16(u + off,         A0 + g);
            cp16(u + 8192 + off,  A1 + g);
            cp16(u + 16384 + off, B0 + g);
            cp16(u + 24576 + off, B1 + g); }
    };

    load(0,0); CPC();
    load(1,1); CPC();
    for (int t=0; t<CK; t++){
        if (t+1<CK){ CPW(1); } else { CPW(0); }
        __syncthreads();
        const uint32_t u = su + (t%3)*STAGE;
        const int q = lane>>3, sub = lane&7;
#pragma unroll
        for (int ks=0; ks<2; ks++){
            uint32_t afh[2][4], afl[2][4];
            const int ch = ks*2 + (q>>1);
#pragma unroll
            for (int mt=0; mt<2; mt++){
                int r = wm*32 + mt*16 + (q&1)*8 + sub;
                uint32_t off = r*64 + ((ch^((r>>1)&3))<<4);
                ldm4(afh[mt], u + off);
                ldm4(afl[mt], u + 8192 + off);
            }
#pragma unroll
            for (int np=0; np<4; np++){
                int r = wn*64 + np*16 + (q&1)*8 + sub;
                uint32_t off = r*64 + ((ch^((r>>1)&3))<<4);
                uint32_t bfh[4], bfl[4];
                ldm4(bfh, u + 16384 + off);
                ldm4(bfl, u + 24576 + off);
#pragma unroll
                for (int nn=0; nn<2; nn++){
                    const int nt = 2*np + nn;
#pragma unroll
                    for (int mt=0; mt<2; mt++){
                        mma16816(acc[mt][nt], afh[mt], bfh[nn], bfh[2+nn]);
                        mma16816(acc[mt][nt], afl[mt], bfh[nn], bfh[2+nn]);
                        mma16816(acc[mt][nt], afh[mt], bfl[nn], bfl[2+nn]);
                    }
                }
            }
        }
        if (t+2<CK){ load(t+2, (t+2)%3); CPC(); }
    }

#pragma unroll
    for (int mt=0; mt<2; mt++){
        const int m0 = bm0 + wm*32 + mt*16 + (lane>>2);
#pragma unroll
        for (int nt=0; nt<8; nt++){
            const int n = bn0 + wn*64 + nt*8 + (lane&3)*2;
            if (MODE == 0){
                float bx = 0.f, by = 0.f;
                if (bias){ bx = bias[n]; by = bias[n+1]; }
                float2 v0 = {acc[mt][nt][0]+bx, acc[mt][nt][1]+by};
                float2 v1 = {acc[mt][nt][2]+bx, acc[mt][nt][3]+by};
                *(float2*)(C + (size_t)m0*ldc + n) = v0;
                *(float2*)(C + (size_t)(m0+8)*ldc + n) = v1;
            } else {
                const int which = n>>10, hh = (n>>6)&15, d = n&63;
                bf16* Dh = (which==0) ? qh : (which==1) ? kh : vh;
                bf16* Dl = (which==0) ? ql : (which==1) ? kl : vl;
                const float sc = (which==0) ? ATTN_SCALE : 1.f;
#pragma unroll
                for (int rr=0; rr<2; rr++){
                    const int m = m0 + rr*8;
                    size_t addr = ((size_t)((m>>11)*16 + hh)*2048 + (m&2047))*64 + d;
                    uint32_t H, L;
                    split2(acc[mt][nt][2*rr]*sc, acc[mt][nt][2*rr+1]*sc, H, L);
                    *(uint32_t*)(Dh + addr) = H;
                    *(uint32_t*)(Dl + addr) = L;
                }
            }
        }
    }
}

// ---------------- fused flash attention (V natural layout + ldmatrix.trans) ----------------
// grid (16 qtiles, 64 bh), 256 thr. smem: Qh/Ql 32K, 2 stages x [Kh|Kl|Vh|Vl] 64K.
__global__ __launch_bounds__(256, 1)
void flash_mma(const bf16* __restrict__ qh, const bf16* __restrict__ ql,
               const bf16* __restrict__ kh, const bf16* __restrict__ kl,
               const bf16* __restrict__ vh, const bf16* __restrict__ vl,
               bf16* __restrict__ oh, bf16* __restrict__ ol){
    extern __shared__ char sm[];
    const uint32_t su = s2u(sm);
    const uint32_t QHs = su, QLs = su + 16384, ST = su + 32768;
    const int tid = threadIdx.x, lane = tid&31, warp = tid>>5;
    const int q2 = lane>>3, sub = lane&7;
    const int qb = blockIdx.x, z = blockIdx.y;

    const char* Qhg = (const char*)(qh + ((size_t)z*NSEQ + (size_t)qb*128)*HD);
    const char* Qlg = (const char*)(ql + ((size_t)z*NSEQ + (size_t)qb*128)*HD);
    const char* Khg = (const char*)(kh + (size_t)z*NSEQ*HD);
    const char* Klg = (const char*)(kl + (size_t)z*NSEQ*HD);
    const char* Vhg = (const char*)(vh + (size_t)z*NSEQ*HD);
    const char* Vlg = (const char*)(vl + (size_t)z*NSEQ*HD);

#pragma unroll
    for (int i=0;i<4;i++){ int id=tid+i*256, r=id>>3, c=id&7;
        uint32_t off = r*128 + ((c^(r&7))<<4);
        cp16(QHs+off, Qhg + (size_t)id*16);
        cp16(QLs+off, Qlg + (size_t)id*16); }
    CPC();

    auto loadkv = [&](int t, int s){
        uint32_t b = ST + s*65536;
#pragma unroll
        for (int i=0;i<4;i++){ int id=tid+i*256, r=id>>3, c=id&7;
            uint32_t off = r*128 + ((c^(r&7))<<4);
            size_t g = (size_t)t*16384 + (size_t)id*16;
            cp16(b+off, Khg+g);        cp16(b+16384+off, Klg+g);
            cp16(b+32768+off, Vhg+g);  cp16(b+49152+off, Vlg+g); }
    };
    loadkv(0,0); CPC();

    CPW(1); __syncthreads();
    uint32_t qhf[4][4], qlf[4][4];
    {
        uint32_t rb = (uint32_t)(warp*16 + (q2&1)*8 + sub)*128;
#pragma unroll
        for (int ks=0;ks<4;ks++){
            uint32_t co = (uint32_t)(((ks*2+(q2>>1))^sub)<<4);
            ldm4(qhf[ks], QHs + rb + co);
            ldm4(qlf[ks], QLs + rb + co);
        }
    }

    float m0=-1e30f, m1=-1e30f, l0=0.f, l1=0.f;
    float oacc[8][4];
#pragma unroll
    for (int i=0;i<8;i++){ oacc[i][0]=0.f; oacc[i][1]=0.f; oacc[i][2]=0.f; oacc[i][3]=0.f; }

    const uint32_t krb = (uint32_t)((q2&1)*8+sub)*128;
    const int vrow = ((lane>>3)&1)*8 + (lane&7);   // trans-ldmatrix row within 16
    const int c16b = lane>>4;                      // 0/1: lower/upper 8 of the 16-d pair

    for (int t=0;t<16;t++){
        const int s = t&1;
        if (t<15){ loadkv(t+1, s^1); CPC(); CPW(1); } else { CPW(0); }
        __syncthreads();
        const uint32_t kb = ST + s*65536;

        float sacc[16][4];
#pragma unroll
        for (int i=0;i<16;i++){ sacc[i][0]=0.f; sacc[i][1]=0.f; sacc[i][2]=0.f; sacc[i][3]=0.f; }

#pragma unroll
        for (int ks=0;ks<4;ks++){
            uint32_t bfr[8][4];
            const uint32_t co = (uint32_t)(((ks*2+(q2>>1))^sub)<<4);
#pragma unroll
            for (int g=0;g<8;g++) ldm4(bfr[g], kb + krb + g*2048 + co);
#pragma unroll
            for (int nt=0;nt<16;nt++) mma16816(sacc[nt], qhf[ks], bfr[nt>>1][nt&1], bfr[nt>>1][2+(nt&1)]);
#pragma unroll
            for (int nt=0;nt<16;nt++) mma16816(sacc[nt], qlf[ks], bfr[nt>>1][nt&1], bfr[nt>>1][2+(nt&1)]);
#pragma unroll
            for (int g=0;g<8;g++) ldm4(bfr[g], kb + 16384 + krb + g*2048 + co);
#pragma unroll
            for (int nt=0;nt<16;nt++) mma16816(sacc[nt], qhf[ks], bfr[nt>>1][nt&1], bfr[nt>>1][2+(nt&1)]);
        }

        float mt0=-1e30f, mt1=-1e30f;
#pragma unroll
        for (int nt=0;nt<16;nt++){
            mt0 = fmaxf(mt0, fmaxf(sacc[nt][0], sacc[nt][1]));
            mt1 = fmaxf(mt1, fmaxf(sacc[nt][2], sacc[nt][3]));
        }
        mt0 = fmaxf(mt0, __shfl_xor_sync(~0u, mt0, 1));
        mt0 = fmaxf(mt0, __shfl_xor_sync(~0u, mt0, 2));
        mt1 = fmaxf(mt1, __shfl_xor_sync(~0u, mt1, 1));
        mt1 = fmaxf(mt1, __shfl_xor_sync(~0u, mt1, 2));
        float nm0 = fmaxf(m0, mt0), nm1 = fmaxf(m1, mt1);
        float a0 = __expf(m0-nm0), a1 = __expf(m1-nm1);
        m0 = nm0; m1 = nm1;
        float s0=0.f, s1=0.f;
#pragma unroll
        for (int nt=0;nt<16;nt++){
            sacc[nt][0]=__expf(sacc[nt][0]-nm0); s0+=sacc[nt][0];
            sacc[nt][1]=__expf(sacc[nt][1]-nm0); s0+=sacc[nt][1];
            sacc[nt][2]=__expf(sacc[nt][2]-nm1); s1+=sacc[nt][2];
            sacc[nt][3]=__expf(sacc[nt][3]-nm1); s1+=sacc[nt][3];
        }
        s0 += __shfl_xor_sync(~0u,s0,1); s0 += __shfl_xor_sync(~0u,s0,2);
        s1 += __shfl_xor_sync(~0u,s1,1); s1 += __shfl_xor_sync(~0u,s1,2);
        l0 = l0*a0 + s0; l1 = l1*a1 + s1;
#pragma unroll
        for (int nd=0;nd<8;nd++){ oacc[nd][0]*=a0; oacc[nd][1]*=a0; oacc[nd][2]*=a1; oacc[nd][3]*=a1; }

        const uint32_t vb = kb + 32768;
#pragma unroll
        for (int j=0;j<8;j++){
            uint32_t pha[4], pla[4];
            split2(sacc[2*j][0],   sacc[2*j][1],   pha[0], pla[0]);
            split2(sacc[2*j][2],   sacc[2*j][3],   pha[1], pla[1]);
            split2(sacc[2*j+1][0], sacc[2*j+1][1], pha[2], pla[2]);
            split2(sacc[2*j+1][2], sacc[2*j+1][3], pha[3], pla[3]);
            const int row = j*16 + vrow;
#pragma unroll
            for (int pp=0; pp<4; pp++){
                const int c16 = pp*2 + c16b;
                const uint32_t off = (uint32_t)(row*128 + ((c16 ^ (row&7))<<4));
                uint32_t bh4[4], bl4[4];
                ldm4t(bh4, vb + off);
                ldm4t(bl4, vb + 16384 + off);
                mma16816(oacc[2*pp],   pha, bh4[0], bh4[1]);
                mma16816(oacc[2*pp],   pla, bh4[0], bh4[1]);
                mma16816(oacc[2*pp],   pha, bl4[0], bl4[1]);
                mma16816(oacc[2*pp+1], pha, bh4[2], bh4[3]);
                mma16816(oacc[2*pp+1], pla, bh4[2], bh4[3]);
                mma16816(oacc[2*pp+1], pha, bl4[2], bl4[3]);
            }
        }
        __syncthreads();
    }

    const float i0 = 1.f/l0, i1 = 1.f/l1;
    const int r0 = warp*16 + (lane>>2);
    bf16* oph = oh + ((size_t)(z>>4)*NSEQ + (size_t)qb*128)*DIMM + (size_t)(z&15)*HD;
    bf16* opl = ol + ((size_t)(z>>4)*NSEQ + (size_t)qb*128)*DIMM + (size_t)(z&15)*HD;
#pragma unroll
    for (int nd=0;nd<8;nd++){
        const int d = nd*8 + (lane&3)*2;
        uint32_t H, L;
        split2(oacc[nd][0]*i0, oacc[nd][1]*i0, H, L);
        *(uint32_t*)(oph + (size_t)r0*DIMM + d) = H;
        *(uint32_t*)(opl + (size_t)r0*DIMM + d) = L;
        split2(oacc[nd][2]*i1, oacc[nd][3]*i1, H, L);
        *(uint32_t*)(oph + (size_t)(r0+8)*DIMM + d) = H;
        *(uint32_t*)(opl + (size_t)(r0+8)*DIMM + d) = L;
    }
}

// ---------------- helpers ----------------
__global__ void split_arr(const float* __restrict__ in, bf16* __restrict__ h, bf16* __restrict__ l, int n4){
    int i = blockIdx.x*blockDim.x + threadIdx.x;
    if (i>=n4) return;
    float4 v = ((const float4*)in)[i];
    __align__(8) bf16 hh[4], ll[4];
    split1(v.x,hh[0],ll[0]); split1(v.y,hh[1],ll[1]); split1(v.z,hh[2],ll[2]); split1(v.w,hh[3],ll[3]);
    ((uint2*)h)[i] = *(uint2*)hh; ((uint2*)l)[i] = *(uint2*)ll;
}

extern "C" void kernel_launch(void* const* d_in, const int* in_sizes, int n_in,
                              void* d_out, int out_size){
    const float* x     = (const float*)d_in[0];
    const float* w_qkv = (const float*)d_in[1];
    const float* w_out = (const float*)d_in[2];
    const float* b_out = (const float*)d_in[3];
    float* out = (float*)d_out;

    bf16 *xh,*xl,*wqh,*wql,*woh,*wol,*qh,*ql,*kh,*kl,*vh,*vl,*ah,*al;
    cudaGetSymbolAddress((void**)&xh,g_xh); cudaGetSymbolAddress((void**)&xl,g_xl);
    cudaGetSymbolAddress((void**)&wqh,g_wqh); cudaGetSymbolAddress((void**)&wql,g_wql);
    cudaGetSymbolAddress((void**)&woh,g_woh); cudaGetSymbolAddress((void**)&wol,g_wol);
    cudaGetSymbolAddress((void**)&qh,g_qh); cudaGetSymbolAddress((void**)&ql,g_ql);
    cudaGetSymbolAddress((void**)&kh,g_kh); cudaGetSymbolAddress((void**)&kl,g_kl);
    cudaGetSymbolAddress((void**)&vh,g_vh); cudaGetSymbolAddress((void**)&vl,g_vl);
    cudaGetSymbolAddress((void**)&ah,g_ah); cudaGetSymbolAddress((void**)&al,g_al);

    cudaFuncSetAttribute(gemm3f<0>, cudaFuncAttributeMaxDynamicSharedMemorySize, 98304);
    cudaFuncSetAttribute(gemm3f<1>, cudaFuncAttributeMaxDynamicSharedMemorySize, 98304);
    cudaFuncSetAttribute(flash_mma, cudaFuncAttributeMaxDynamicSharedMemorySize, 163840);

    split_arr<<<8192*1024/4/256,256>>>(x, xh, xl, 8192*1024/4);
    split_arr<<<3072*1024/4/256,256>>>(w_qkv, wqh, wql, 3072*1024/4);
    split_arr<<<1024*1024/4/256,256>>>(w_out, woh, wol, 1024*1024/4);

    // 1) QKV projection, epilogue writes q/k/v per-head split-bf16 directly
    gemm3f<1><<<dim3(24,64),256,98304>>>(xh,xl,wqh,wql, nullptr,nullptr,
                                         qh,ql,kh,kl,vh,vl, 1024, 0);

    // 2) fused flash attention -> ah/al
    flash_mma<<<dim3(16,64),256,163840>>>(qh,ql,kh,kl,vh,vl,ah,al);

    // 3) out = att @ w_out^T + b_out
    gemm3f<0><<<dim3(8,64),256,98304>>>(ah,al,woh,wol, out, b_out,
                                        nullptr,nullptr,nullptr,nullptr,nullptr,nullptr,
                                        1024, 1024);
}

// round 8
// speedup vs baseline: 9.6012x; 1.4631x over previous
#include <cuda_runtime.h>
#include <cuda_fp16.h>
#include <cstdint>
#include <cstddef>

#define DIMM 1024
#define NSEQ 2048
#define NB   4
#define NH   16
#define HD   64
#define NBH  (NB*NH)
#define ATTN_SCALE 0.03125f
#define BK 32

__device__ half g_xh[(size_t)NB*NSEQ*DIMM],  g_xl[(size_t)NB*NSEQ*DIMM];
__device__ half g_wq[(size_t)3*DIMM*DIMM];
__device__ half g_wo[(size_t)DIMM*DIMM];
__device__ half g_qh[(size_t)NBH*NSEQ*HD],   g_ql[(size_t)NBH*NSEQ*HD];
__device__ half g_kf[(size_t)NBH*NSEQ*HD];
__device__ half g_vf[(size_t)NBH*NSEQ*HD];
__device__ half g_ah[(size_t)NB*NSEQ*DIMM],  g_al[(size_t)NB*NSEQ*DIMM];

__device__ __forceinline__ uint32_t s2u(const void* p){
    uint32_t a; asm("{ .reg .u64 t; cvta.to.shared.u64 t, %1; cvt.u32.u64 %0, t; }":"=r"(a):"l"(p)); return a;
}
__device__ __forceinline__ void cp16(uint32_t s, const void* g){
    asm volatile("cp.async.cg.shared.global [%0], [%1], 16;"::"r"(s),"l"(g));
}
#define CPC() asm volatile("cp.async.commit_group;":::"memory")
#define CPW(n) asm volatile("cp.async.wait_group %0;"::"n"(n):"memory")

__device__ __forceinline__ void ldm4(uint32_t* f, uint32_t a){
    asm volatile("ldmatrix.sync.aligned.m8n8.x4.shared.b16 {%0,%1,%2,%3}, [%4];"
        :"=r"(f[0]),"=r"(f[1]),"=r"(f[2]),"=r"(f[3]):"r"(a));
}
__device__ __forceinline__ void ldm4t(uint32_t* f, uint32_t a){
    asm volatile("ldmatrix.sync.aligned.m8n8.x4.trans.shared.b16 {%0,%1,%2,%3}, [%4];"
        :"=r"(f[0]),"=r"(f[1]),"=r"(f[2]),"=r"(f[3]):"r"(a));
}
__device__ __forceinline__ void mma16816(float* d, const uint32_t* a, uint32_t b0, uint32_t b1){
    asm volatile("mma.sync.aligned.m16n8k16.row.col.f32.f16.f16.f32 "
        "{%0,%1,%2,%3}, {%4,%5,%6,%7}, {%8,%9}, {%0,%1,%2,%3};"
        :"+f"(d[0]),"+f"(d[1]),"+f"(d[2]),"+f"(d[3])
        :"r"(a[0]),"r"(a[1]),"r"(a[2]),"r"(a[3]),"r"(b0),"r"(b1));
}
__device__ __forceinline__ uint32_t hpack2(float a, float b){
    __half2 h = __floats2half2_rn(a, b);
    return *(uint32_t*)&h;
}
__device__ __forceinline__ void hsplit2(float a, float b, uint32_t& H, uint32_t& L){
    __half2 h = __floats2half2_rn(a, b);
    float2 hf = __half22float2(h);
    __half2 l = __floats2half2_rn(a - hf.x, b - hf.y);
    H = *(uint32_t*)&h; L = *(uint32_t*)&l;
}

// ---------------- 2-term fp16 projection GEMM, 3-stage pipeline ----------------
// C = (Ah+Al) . Bf^T (B pre-rounded to fp16). 128x128 tile, BK=32.
// MODE 0: fp32 C (+bias).  MODE 1: write q (scaled, split) / k / v per-head.
template<int MODE>
__global__ __launch_bounds__(256, 2)
void gemm2f(const half* __restrict__ Ah, const half* __restrict__ Al,
            const half* __restrict__ Bf,
            float* __restrict__ C, const float* __restrict__ bias,
            half* __restrict__ qh, half* __restrict__ ql,
            half* __restrict__ kf, half* __restrict__ vf,
            int K, int ldc){
    constexpr int STAGE = 24576;   // Ah 8K | Al 8K | Bf 8K
    extern __shared__ __align__(256) char smem[];
    const uint32_t su = s2u(smem);

    const int tid = threadIdx.x, lane = tid&31, warp = tid>>5;
    const int wm = warp&3, wn = warp>>2;
    const int bn0 = blockIdx.x*128, bm0 = blockIdx.y*128;
    const size_t lda = (size_t)K*2;

    const char* A0 = (const char*)(Ah + (size_t)bm0*K);
    const char* A1 = (const char*)(Al + (size_t)bm0*K);
    const char* B0 = (const char*)(Bf + (size_t)bn0*K);
    const int CK = K/BK;

    float acc[2][8][4];
#pragma unroll
    for (int i=0;i<2;i++)
#pragma unroll
        for (int j=0;j<8;j++)
#pragma unroll
            for (int k=0;k<4;k++) acc[i][j][k] = 0.f;

    auto load = [&](int t, int s){
        const uint32_t u = su + s*STAGE;
        const size_t ko = (size_t)t*64;
#pragma unroll
        for (int i=0;i<2;i++){ int id=tid+i*256, r=id>>2, c=id&3;
            uint32_t off = r*64 + ((c^((r>>1)&3))<<4);
            size_t g = (size_t)r*lda + c*16 + ko;
            cp16(u + off,         A0 + g);
            cp16(u + 8192 + off,  A1 + g);
            cp16(u + 16384 + off, B0 + g); }
    };

    load(0,0); CPC();
    load(1,1); CPC();
    for (int t=0; t<CK; t++){
        if (t+1<CK){ CPW(1); } else { CPW(0); }
        __syncthreads();
        const uint32_t u = su + (t%3)*STAGE;
        const int q = lane>>3, sub = lane&7;
#pragma unroll
        for (int ks=0; ks<2; ks++){
            uint32_t afh[2][4], afl[2][4];
            const int ch = ks*2 + (q>>1);
#pragma unroll
            for (int mt=0; mt<2; mt++){
                int r = wm*32 + mt*16 + (q&1)*8 + sub;
                uint32_t off = r*64 + ((ch^((r>>1)&3))<<4);
                ldm4(afh[mt], u + off);
                ldm4(afl[mt], u + 8192 + off);
            }
#pragma unroll
            for (int np=0; np<4; np++){
                int r = wn*64 + np*16 + (q&1)*8 + sub;
                uint32_t off = r*64 + ((ch^((r>>1)&3))<<4);
                uint32_t bfh[4];
                ldm4(bfh, u + 16384 + off);
#pragma unroll
                for (int nn=0; nn<2; nn++){
                    const int nt = 2*np + nn;
#pragma unroll
                    for (int mt=0; mt<2; mt++){
                        mma16816(acc[mt][nt], afh[mt], bfh[nn], bfh[2+nn]);
                        mma16816(acc[mt][nt], afl[mt], bfh[nn], bfh[2+nn]);
                    }
                }
            }
        }
        if (t+2<CK){ load(t+2, (t+2)%3); CPC(); }
    }

#pragma unroll
    for (int mt=0; mt<2; mt++){
        const int m0 = bm0 + wm*32 + mt*16 + (lane>>2);
#pragma unroll
        for (int nt=0; nt<8; nt++){
            const int n = bn0 + wn*64 + nt*8 + (lane&3)*2;
            if (MODE == 0){
                float bx = 0.f, by = 0.f;
                if (bias){ bx = bias[n]; by = bias[n+1]; }
                float2 v0 = {acc[mt][nt][0]+bx, acc[mt][nt][1]+by};
                float2 v1 = {acc[mt][nt][2]+bx, acc[mt][nt][3]+by};
                *(float2*)(C + (size_t)m0*ldc + n) = v0;
                *(float2*)(C + (size_t)(m0+8)*ldc + n) = v1;
            } else {
                const int which = n>>10, hh = (n>>6)&15, d = n&63;
#pragma unroll
                for (int rr=0; rr<2; rr++){
                    const int m = m0 + rr*8;
                    size_t addr = ((size_t)((m>>11)*16 + hh)*2048 + (m&2047))*64 + d;
                    float va = acc[mt][nt][2*rr], vb = acc[mt][nt][2*rr+1];
                    if (which == 0){
                        uint32_t H, L;
                        hsplit2(va*ATTN_SCALE, vb*ATTN_SCALE, H, L);
                        *(uint32_t*)(qh + addr) = H;
                        *(uint32_t*)(ql + addr) = L;
                    } else if (which == 1){
                        *(uint32_t*)(kf + addr) = hpack2(va, vb);
                    } else {
                        *(uint32_t*)(vf + addr) = hpack2(va, vb);
                    }
                }
            }
        }
    }
}

// ---------------- fused flash attention, fp16 2-term ----------------
// grid (16 qtiles, 64 bh), 256 thr. smem: Qh 16K | Ql 16K | 2 x [Kf 16K | Vf 16K]
__global__ __launch_bounds__(256, 1)
void flash_mma(const half* __restrict__ qh, const half* __restrict__ ql,
               const half* __restrict__ kf, const half* __restrict__ vf,
               half* __restrict__ oh, half* __restrict__ ol){
    extern __shared__ char sm[];
    const uint32_t su = s2u(sm);
    const uint32_t QHs = su, QLs = su + 16384, ST = su + 32768;
    const int tid = threadIdx.x, lane = tid&31, warp = tid>>5;
    const int q2 = lane>>3, sub = lane&7;
    const int qb = blockIdx.x, z = blockIdx.y;

    const char* Qhg = (const char*)(qh + ((size_t)z*NSEQ + (size_t)qb*128)*HD);
    const char* Qlg = (const char*)(ql + ((size_t)z*NSEQ + (size_t)qb*128)*HD);
    const char* Kg  = (const char*)(kf + (size_t)z*NSEQ*HD);
    const char* Vg  = (const char*)(vf + (size_t)z*NSEQ*HD);

#pragma unroll
    for (int i=0;i<4;i++){ int id=tid+i*256, r=id>>3, c=id&7;
        uint32_t off = r*128 + ((c^(r&7))<<4);
        cp16(QHs+off, Qhg + (size_t)id*16);
        cp16(QLs+off, Qlg + (size_t)id*16); }
    CPC();

    auto loadkv = [&](int t, int s){
        uint32_t b = ST + s*32768;
#pragma unroll
        for (int i=0;i<4;i++){ int id=tid+i*256, r=id>>3, c=id&7;
            uint32_t off = r*128 + ((c^(r&7))<<4);
            size_t g = (size_t)t*16384 + (size_t)id*16;
            cp16(b+off, Kg+g);  cp16(b+16384+off, Vg+g); }
    };
    loadkv(0,0); CPC();

    CPW(1); __syncthreads();
    uint32_t qhf[4][4], qlf[4][4];
    {
        uint32_t rb = (uint32_t)(warp*16 + (q2&1)*8 + sub)*128;
#pragma unroll
        for (int ks=0;ks<4;ks++){
            uint32_t co = (uint32_t)(((ks*2+(q2>>1))^sub)<<4);
            ldm4(qhf[ks], QHs + rb + co);
            ldm4(qlf[ks], QLs + rb + co);
        }
    }

    float m0=-1e30f, m1=-1e30f, l0=0.f, l1=0.f;
    float oacc[8][4];
#pragma unroll
    for (int i=0;i<8;i++){ oacc[i][0]=0.f; oacc[i][1]=0.f; oacc[i][2]=0.f; oacc[i][3]=0.f; }

    const uint32_t krb = (uint32_t)((q2&1)*8+sub)*128;
    const int vrow = ((lane>>3)&1)*8 + (lane&7);
    const int c16b = lane>>4;

    for (int t=0;t<16;t++){
        const int s = t&1;
        if (t<15){ loadkv(t+1, s^1); CPC(); CPW(1); } else { CPW(0); }
        __syncthreads();
        const uint32_t kb = ST + s*32768;

        float sacc[16][4];
#pragma unroll
        for (int i=0;i<16;i++){ sacc[i][0]=0.f; sacc[i][1]=0.f; sacc[i][2]=0.f; sacc[i][3]=0.f; }

#pragma unroll
        for (int ks=0;ks<4;ks++){
            uint32_t bfr[8][4];
            const uint32_t co = (uint32_t)(((ks*2+(q2>>1))^sub)<<4);
#pragma unroll
            for (int g=0;g<8;g++) ldm4(bfr[g], kb + krb + g*2048 + co);
#pragma unroll
            for (int nt=0;nt<16;nt++) mma16816(sacc[nt], qhf[ks], bfr[nt>>1][nt&1], bfr[nt>>1][2+(nt&1)]);
#pragma unroll
            for (int nt=0;nt<16;nt++) mma16816(sacc[nt], qlf[ks], bfr[nt>>1][nt&1], bfr[nt>>1][2+(nt&1)]);
        }

        float mt0=-1e30f, mt1=-1e30f;
#pragma unroll
        for (int nt=0;nt<16;nt++){
            mt0 = fmaxf(mt0, fmaxf(sacc[nt][0], sacc[nt][1]));
            mt1 = fmaxf(mt1, fmaxf(sacc[nt][2], sacc[nt][3]));
        }
        mt0 = fmaxf(mt0, __shfl_xor_sync(~0u, mt0, 1));
        mt0 = fmaxf(mt0, __shfl_xor_sync(~0u, mt0, 2));
        mt1 = fmaxf(mt1, __shfl_xor_sync(~0u, mt1, 1));
        mt1 = fmaxf(mt1, __shfl_xor_sync(~0u, mt1, 2));
        float nm0 = fmaxf(m0, mt0), nm1 = fmaxf(m1, mt1);
        float a0 = __expf(m0-nm0), a1 = __expf(m1-nm1);
        m0 = nm0; m1 = nm1;
        float s0=0.f, s1=0.f;
#pragma unroll
        for (int nt=0;nt<16;nt++){
            sacc[nt][0]=__expf(sacc[nt][0]-nm0); s0+=sacc[nt][0];
            sacc[nt][1]=__expf(sacc[nt][1]-nm0); s0+=sacc[nt][1];
            sacc[nt][2]=__expf(sacc[nt][2]-nm1); s1+=sacc[nt][2];
            sacc[nt][3]=__expf(sacc[nt][3]-nm1); s1+=sacc[nt][3];
        }
        s0 += __shfl_xor_sync(~0u,s0,1); s0 += __shfl_xor_sync(~0u,s0,2);
        s1 += __shfl_xor_sync(~0u,s1,1); s1 += __shfl_xor_sync(~0u,s1,2);
        l0 = l0*a0 + s0; l1 = l1*a1 + s1;
#pragma unroll
        for (int nd=0;nd<8;nd++){ oacc[nd][0]*=a0; oacc[nd][1]*=a0; oacc[nd][2]*=a1; oacc[nd][3]*=a1; }

        const uint32_t vb = kb + 16384;
#pragma unroll
        for (int j=0;j<8;j++){
            uint32_t pha[4], pla[4];
            hsplit2(sacc[2*j][0],   sacc[2*j][1],   pha[0], pla[0]);
            hsplit2(sacc[2*j][2],   sacc[2*j][3],   pha[1], pla[1]);
            hsplit2(sacc[2*j+1][0], sacc[2*j+1][1], pha[2], pla[2]);
            hsplit2(sacc[2*j+1][2], sacc[2*j+1][3], pha[3], pla[3]);
            const int row = j*16 + vrow;
#pragma unroll
            for (int pp=0; pp<4; pp++){
                const int c16 = pp*2 + c16b;
                const uint32_t off = (uint32_t)(row*128 + ((c16 ^ (row&7))<<4));
                uint32_t bh4[4];
                ldm4t(bh4, vb + off);
                mma16816(oacc[2*pp],   pha, bh4[0], bh4[1]);
                mma16816(oacc[2*pp],   pla, bh4[0], bh4[1]);
                mma16816(oacc[2*pp+1], pha, bh4[2], bh4[3]);
                mma16816(oacc[2*pp+1], pla, bh4[2], bh4[3]);
            }
        }
        __syncthreads();
    }

    const float i0 = 1.f/l0, i1 = 1.f/l1;
    const int r0 = warp*16 + (lane>>2);
    half* oph = oh + ((size_t)(z>>4)*NSEQ + (size_t)qb*128)*DIMM + (size_t)(z&15)*HD;
    half* opl = ol + ((size_t)(z>>4)*NSEQ + (size_t)qb*128)*DIMM + (size_t)(z&15)*HD;
#pragma unroll
    for (int nd=0;nd<8;nd++){
        const int d = nd*8 + (lane&3)*2;
        uint32_t H, L;
        hsplit2(oacc[nd][0]*i0, oacc[nd][1]*i0, H, L);
        *(uint32_t*)(oph + (size_t)r0*DIMM + d) = H;
        *(uint32_t*)(opl + (size_t)r0*DIMM + d) = L;
        hsplit2(oacc[nd][2]*i1, oacc[nd][3]*i1, H, L);
        *(uint32_t*)(oph + (size_t)(r0+8)*DIMM + d) = H;
        *(uint32_t*)(opl + (size_t)(r0+8)*DIMM + d) = L;
    }
}

// ---------------- helpers ----------------
__global__ void split_arr(const float* __restrict__ in, half* __restrict__ h, half* __restrict__ l, int n4){
    int i = blockIdx.x*blockDim.x + threadIdx.x;
    if (i>=n4) return;
    float4 v = ((const float4*)in)[i];
    uint32_t H0,L0,H1,L1;
    hsplit2(v.x, v.y, H0, L0);
    hsplit2(v.z, v.w, H1, L1);
    ((uint2*)h)[i] = make_uint2(H0,H1);
    ((uint2*)l)[i] = make_uint2(L0,L1);
}
__global__ void round_arr(const float* __restrict__ in, half* __restrict__ o, int n4){
    int i = blockIdx.x*blockDim.x + threadIdx.x;
    if (i>=n4) return;
    float4 v = ((const float4*)in)[i];
    ((uint2*)o)[i] = make_uint2(hpack2(v.x,v.y), hpack2(v.z,v.w));
}

extern "C" void kernel_launch(void* const* d_in, const int* in_sizes, int n_in,
                              void* d_out, int out_size){
    const float* x     = (const float*)d_in[0];
    const float* w_qkv = (const float*)d_in[1];
    const float* w_out = (const float*)d_in[2];
    const float* b_out = (const float*)d_in[3];
    float* out = (float*)d_out;

    half *xh,*xl,*wq,*wo,*qh,*ql,*kf,*vf,*ah,*al;
    cudaGetSymbolAddress((void**)&xh,g_xh); cudaGetSymbolAddress((void**)&xl,g_xl);
    cudaGetSymbolAddress((void**)&wq,g_wq); cudaGetSymbolAddress((void**)&wo,g_wo);
    cudaGetSymbolAddress((void**)&qh,g_qh); cudaGetSymbolAddress((void**)&ql,g_ql);
    cudaGetSymbolAddress((void**)&kf,g_kf); cudaGetSymbolAddress((void**)&vf,g_vf);
    cudaGetSymbolAddress((void**)&ah,g_ah); cudaGetSymbolAddress((void**)&al,g_al);

    cudaFuncSetAttribute(gemm2f<0>, cudaFuncAttributeMaxDynamicSharedMemorySize, 73728);
    cudaFuncSetAttribute(gemm2f<1>, cudaFuncAttributeMaxDynamicSharedMemorySize, 73728);
    cudaFuncSetAttribute(flash_mma, cudaFuncAttributeMaxDynamicSharedMemorySize, 98304);

    split_arr<<<8192*1024/4/256,256>>>(x, xh, xl, 8192*1024/4);
    round_arr<<<3072*1024/4/256,256>>>(w_qkv, wq, 3072*1024/4);
    round_arr<<<1024*1024/4/256,256>>>(w_out, wo, 1024*1024/4);

    // 1) QKV projection -> q (scaled, split fp16) / k / v per-head
    gemm2f<1><<<dim3(24,64),256,73728>>>(xh,xl,wq, nullptr,nullptr,
                                         qh,ql,kf,vf, 1024, 0);

    // 2) fused flash attention -> ah/al (fp16 hi/lo)
    flash_mma<<<dim3(16,64),256,98304>>>(qh,ql,kf,vf,ah,al);

    // 3) out = att @ w_out^T + b_out
    gemm2f<0><<<dim3(8,64),256,73728>>>(ah,al,wo, out, b_out,
                                        nullptr,nullptr,nullptr,nullptr, 1024, 1024);
}

// round 9
// speedup vs baseline: 11.5802x; 1.2061x over previous
#include <cuda_runtime.h>
#include <cuda_fp16.h>
#include <cstdint>
#include <cstddef>

#define DIMM 1024
#define NSEQ 2048
#define NB   4
#define NH   16
#define HD   64
#define NBH  (NB*NH)
#define ATTN_SCALE 0.03125f
#define BK 32

__device__ half g_xh[(size_t)NB*NSEQ*DIMM],  g_xl[(size_t)NB*NSEQ*DIMM];
__device__ half g_wq[(size_t)3*DIMM*DIMM];
__device__ half g_wo[(size_t)DIMM*DIMM];
__device__ half g_qf[(size_t)NBH*NSEQ*HD];
__device__ half g_kf[(size_t)NBH*NSEQ*HD];
__device__ half g_vf[(size_t)NBH*NSEQ*HD];
__device__ half g_ah[(size_t)NB*NSEQ*DIMM],  g_al[(size_t)NB*NSEQ*DIMM];

__device__ __forceinline__ uint32_t s2u(const void* p){
    uint32_t a; asm("{ .reg .u64 t; cvta.to.shared.u64 t, %1; cvt.u32.u64 %0, t; }":"=r"(a):"l"(p)); return a;
}
__device__ __forceinline__ void cp16(uint32_t s, const void* g){
    asm volatile("cp.async.cg.shared.global [%0], [%1], 16;"::"r"(s),"l"(g));
}
#define CPC() asm volatile("cp.async.commit_group;":::"memory")
#define CPW(n) asm volatile("cp.async.wait_group %0;"::"n"(n):"memory")

__device__ __forceinline__ void ldm4(uint32_t* f, uint32_t a){
    asm volatile("ldmatrix.sync.aligned.m8n8.x4.shared.b16 {%0,%1,%2,%3}, [%4];"
        :"=r"(f[0]),"=r"(f[1]),"=r"(f[2]),"=r"(f[3]):"r"(a));
}
__device__ __forceinline__ void ldm4t(uint32_t* f, uint32_t a){
    asm volatile("ldmatrix.sync.aligned.m8n8.x4.trans.shared.b16 {%0,%1,%2,%3}, [%4];"
        :"=r"(f[0]),"=r"(f[1]),"=r"(f[2]),"=r"(f[3]):"r"(a));
}
__device__ __forceinline__ void mma16816(float* d, const uint32_t* a, uint32_t b0, uint32_t b1){
    asm volatile("mma.sync.aligned.m16n8k16.row.col.f32.f16.f16.f32 "
        "{%0,%1,%2,%3}, {%4,%5,%6,%7}, {%8,%9}, {%0,%1,%2,%3};"
        :"+f"(d[0]),"+f"(d[1]),"+f"(d[2]),"+f"(d[3])
        :"r"(a[0]),"r"(a[1]),"r"(a[2]),"r"(a[3]),"r"(b0),"r"(b1));
}
__device__ __forceinline__ uint32_t hpack2(float a, float b){
    __half2 h = __floats2half2_rn(a, b);
    return *(uint32_t*)&h;
}
__device__ __forceinline__ void hsplit2(float a, float b, uint32_t& H, uint32_t& L){
    __half2 h = __floats2half2_rn(a, b);
    float2 hf = __half22float2(h);
    __half2 l = __floats2half2_rn(a - hf.x, b - hf.y);
    H = *(uint32_t*)&h; L = *(uint32_t*)&l;
}

// ---------------- 2-term fp16 projection GEMM, 3-stage pipeline ----------------
// C = (Ah+Al) . Bf^T. MODE 0: fp32 C (+bias). MODE 1: q (scaled, rounded)/k/v per-head.
template<int MODE>
__global__ __launch_bounds__(256, 2)
void gemm2f(const half* __restrict__ Ah, const half* __restrict__ Al,
            const half* __restrict__ Bf,
            float* __restrict__ C, const float* __restrict__ bias,
            half* __restrict__ qf, half* __restrict__ kf, half* __restrict__ vf,
            int K, int ldc){
    constexpr int STAGE = 24576;
    extern __shared__ __align__(256) char smem[];
    const uint32_t su = s2u(smem);

    const int tid = threadIdx.x, lane = tid&31, warp = tid>>5;
    const int wm = warp&3, wn = warp>>2;
    const int bn0 = blockIdx.x*128, bm0 = blockIdx.y*128;
    const size_t lda = (size_t)K*2;

    const char* A0 = (const char*)(Ah + (size_t)bm0*K);
    const char* A1 = (const char*)(Al + (size_t)bm0*K);
    const char* B0 = (const char*)(Bf + (size_t)bn0*K);
    const int CK = K/BK;

    float acc[2][8][4];
#pragma unroll
    for (int i=0;i<2;i++)
#pragma unroll
        for (int j=0;j<8;j++)
#pragma unroll
            for (int k=0;k<4;k++) acc[i][j][k] = 0.f;

    auto load = [&](int t, int s){
        const uint32_t u = su + s*STAGE;
        const size_t ko = (size_t)t*64;
#pragma unroll
        for (int i=0;i<2;i++){ int id=tid+i*256, r=id>>2, c=id&3;
            uint32_t off = r*64 + ((c^((r>>1)&3))<<4);
            size_t g = (size_t)r*lda + c*16 + ko;
            cp16(u + off,         A0 + g);
            cp16(u + 8192 + off,  A1 + g);
            cp16(u + 16384 + off, B0 + g); }
    };

    load(0,0); CPC();
    load(1,1); CPC();
    for (int t=0; t<CK; t++){
        if (t+1<CK){ CPW(1); } else { CPW(0); }
        __syncthreads();
        const uint32_t u = su + (t%3)*STAGE;
        const int q = lane>>3, sub = lane&7;
#pragma unroll
        for (int ks=0; ks<2; ks++){
            uint32_t afh[2][4], afl[2][4];
            const int ch = ks*2 + (q>>1);
#pragma unroll
            for (int mt=0; mt<2; mt++){
                int r = wm*32 + mt*16 + (q&1)*8 + sub;
                uint32_t off = r*64 + ((ch^((r>>1)&3))<<4);
                ldm4(afh[mt], u + off);
                ldm4(afl[mt], u + 8192 + off);
            }
#pragma unroll
            for (int np=0; np<4; np++){
                int r = wn*64 + np*16 + (q&1)*8 + sub;
                uint32_t off = r*64 + ((ch^((r>>1)&3))<<4);
                uint32_t bfh[4];
                ldm4(bfh, u + 16384 + off);
#pragma unroll
                for (int nn=0; nn<2; nn++){
                    const int nt = 2*np + nn;
#pragma unroll
                    for (int mt=0; mt<2; mt++){
                        mma16816(acc[mt][nt], afh[mt], bfh[nn], bfh[2+nn]);
                        mma16816(acc[mt][nt], afl[mt], bfh[nn], bfh[2+nn]);
                    }
                }
            }
        }
        if (t+2<CK){ load(t+2, (t+2)%3); CPC(); }
    }

#pragma unroll
    for (int mt=0; mt<2; mt++){
        const int m0 = bm0 + wm*32 + mt*16 + (lane>>2);
#pragma unroll
        for (int nt=0; nt<8; nt++){
            const int n = bn0 + wn*64 + nt*8 + (lane&3)*2;
            if (MODE == 0){
                float bx = 0.f, by = 0.f;
                if (bias){ bx = bias[n]; by = bias[n+1]; }
                float2 v0 = {acc[mt][nt][0]+bx, acc[mt][nt][1]+by};
                float2 v1 = {acc[mt][nt][2]+bx, acc[mt][nt][3]+by};
                *(float2*)(C + (size_t)m0*ldc + n) = v0;
                *(float2*)(C + (size_t)(m0+8)*ldc + n) = v1;
            } else {
                const int which = n>>10, hh = (n>>6)&15, d = n&63;
                half* D = (which==0) ? qf : (which==1) ? kf : vf;
                const float sc = (which==0) ? ATTN_SCALE : 1.f;
#pragma unroll
                for (int rr=0; rr<2; rr++){
                    const int m = m0 + rr*8;
                    size_t addr = ((size_t)((m>>11)*16 + hh)*2048 + (m&2047))*64 + d;
                    *(uint32_t*)(D + addr) = hpack2(acc[mt][nt][2*rr]*sc, acc[mt][nt][2*rr+1]*sc);
                }
            }
        }
    }
}

// ---------------- fused flash attention, fp16 single-term QK + PV ----------------
// grid (16 qtiles, 64 bh), 256 thr. smem: Qf 16K | 2 x [Kf 16K | Vf 16K] = 80K
__global__ __launch_bounds__(256, 1)
void flash_mma(const half* __restrict__ qf, const half* __restrict__ kf,
               const half* __restrict__ vf,
               half* __restrict__ oh, half* __restrict__ ol){
    extern __shared__ char sm[];
    const uint32_t su = s2u(sm);
    const uint32_t Qs = su, ST = su + 16384;
    const int tid = threadIdx.x, lane = tid&31, warp = tid>>5;
    const int q2 = lane>>3, sub = lane&7;
    const int qb = blockIdx.x, z = blockIdx.y;

    const char* Qg = (const char*)(qf + ((size_t)z*NSEQ + (size_t)qb*128)*HD);
    const char* Kg = (const char*)(kf + (size_t)z*NSEQ*HD);
    const char* Vg = (const char*)(vf + (size_t)z*NSEQ*HD);

#pragma unroll
    for (int i=0;i<4;i++){ int id=tid+i*256, r=id>>3, c=id&7;
        uint32_t off = r*128 + ((c^(r&7))<<4);
        cp16(Qs+off, Qg + (size_t)id*16); }
    CPC();

    auto loadkv = [&](int t, int s){
        uint32_t b = ST + s*32768;
#pragma unroll
        for (int i=0;i<4;i++){ int id=tid+i*256, r=id>>3, c=id&7;
            uint32_t off = r*128 + ((c^(r&7))<<4);
            size_t g = (size_t)t*16384 + (size_t)id*16;
            cp16(b+off, Kg+g);  cp16(b+16384+off, Vg+g); }
    };
    loadkv(0,0); CPC();

    CPW(1); __syncthreads();
    uint32_t qff[4][4];
    {
        uint32_t rb = (uint32_t)(warp*16 + (q2&1)*8 + sub)*128;
#pragma unroll
        for (int ks=0;ks<4;ks++){
            uint32_t co = (uint32_t)(((ks*2+(q2>>1))^sub)<<4);
            ldm4(qff[ks], Qs + rb + co);
        }
    }

    float m0=-1e30f, m1=-1e30f, l0=0.f, l1=0.f;
    float oacc[8][4];
#pragma unroll
    for (int i=0;i<8;i++){ oacc[i][0]=0.f; oacc[i][1]=0.f; oacc[i][2]=0.f; oacc[i][3]=0.f; }

    const uint32_t krb = (uint32_t)((q2&1)*8+sub)*128;
    const int vrow = ((lane>>3)&1)*8 + (lane&7);
    const int c16b = lane>>4;

    for (int t=0;t<16;t++){
        const int s = t&1;
        if (t<15){ loadkv(t+1, s^1); CPC(); CPW(1); } else { CPW(0); }
        __syncthreads();
        const uint32_t kb = ST + s*32768;

        float sacc[16][4];
#pragma unroll
        for (int i=0;i<16;i++){ sacc[i][0]=0.f; sacc[i][1]=0.f; sacc[i][2]=0.f; sacc[i][3]=0.f; }

#pragma unroll
        for (int ks=0;ks<4;ks++){
            uint32_t bfr[8][4];
            const uint32_t co = (uint32_t)(((ks*2+(q2>>1))^sub)<<4);
#pragma unroll
            for (int g=0;g<8;g++) ldm4(bfr[g], kb + krb + g*2048 + co);
#pragma unroll
            for (int nt=0;nt<16;nt++) mma16816(sacc[nt], qff[ks], bfr[nt>>1][nt&1], bfr[nt>>1][2+(nt&1)]);
        }

        float mt0=-1e30f, mt1=-1e30f;
#pragma unroll
        for (int nt=0;nt<16;nt++){
            mt0 = fmaxf(mt0, fmaxf(sacc[nt][0], sacc[nt][1]));
            mt1 = fmaxf(mt1, fmaxf(sacc[nt][2], sacc[nt][3]));
        }
        mt0 = fmaxf(mt0, __shfl_xor_sync(~0u, mt0, 1));
        mt0 = fmaxf(mt0, __shfl_xor_sync(~0u, mt0, 2));
        mt1 = fmaxf(mt1, __shfl_xor_sync(~0u, mt1, 1));
        mt1 = fmaxf(mt1, __shfl_xor_sync(~0u, mt1, 2));
        float nm0 = fmaxf(m0, mt0), nm1 = fmaxf(m1, mt1);
        float a0 = __expf(m0-nm0), a1 = __expf(m1-nm1);
        m0 = nm0; m1 = nm1;
        float s0=0.f, s1=0.f;
#pragma unroll
        for (int nt=0;nt<16;nt++){
            sacc[nt][0]=__expf(sacc[nt][0]-nm0); s0+=sacc[nt][0];
            sacc[nt][1]=__expf(sacc[nt][1]-nm0); s0+=sacc[nt][1];
            sacc[nt][2]=__expf(sacc[nt][2]-nm1); s1+=sacc[nt][2];
            sacc[nt][3]=__expf(sacc[nt][3]-nm1); s1+=sacc[nt][3];
        }
        s0 += __shfl_xor_sync(~0u,s0,1); s0 += __shfl_xor_sync(~0u,s0,2);
        s1 += __shfl_xor_sync(~0u,s1,1); s1 += __shfl_xor_sync(~0u,s1,2);
        l0 = l0*a0 + s0; l1 = l1*a1 + s1;
#pragma unroll
        for (int nd=0;nd<8;nd++){ oacc[nd][0]*=a0; oacc[nd][1]*=a0; oacc[nd][2]*=a1; oacc[nd][3]*=a1; }

        const uint32_t vb = kb + 16384;
#pragma unroll
        for (int j=0;j<8;j++){
            uint32_t pha[4];
            pha[0] = hpack2(sacc[2*j][0],   sacc[2*j][1]);
            pha[1] = hpack2(sacc[2*j][2],   sacc[2*j][3]);
            pha[2] = hpack2(sacc[2*j+1][0], sacc[2*j+1][1]);
            pha[3] = hpack2(sacc[2*j+1][2], sacc[2*j+1][3]);
            const int row = j*16 + vrow;
#pragma unroll
            for (int pp=0; pp<4; pp++){
                const int c16 = pp*2 + c16b;
                const uint32_t off = (uint32_t)(row*128 + ((c16 ^ (row&7))<<4));
                uint32_t bh4[4];
                ldm4t(bh4, vb + off);
                mma16816(oacc[2*pp],   pha, bh4[0], bh4[1]);
                mma16816(oacc[2*pp+1], pha, bh4[2], bh4[3]);
            }
        }
        __syncthreads();
    }

    const float i0 = 1.f/l0, i1 = 1.f/l1;
    const int r0 = warp*16 + (lane>>2);
    half* oph = oh + ((size_t)(z>>4)*NSEQ + (size_t)qb*128)*DIMM + (size_t)(z&15)*HD;
    half* opl = ol + ((size_t)(z>>4)*NSEQ + (size_t)qb*128)*DIMM + (size_t)(z&15)*HD;
#pragma unroll
    for (int nd=0;nd<8;nd++){
        const int d = nd*8 + (lane&3)*2;
        uint32_t H, L;
        hsplit2(oacc[nd][0]*i0, oacc[nd][1]*i0, H, L);
        *(uint32_t*)(oph + (size_t)r0*DIMM + d) = H;
        *(uint32_t*)(opl + (size_t)r0*DIMM + d) = L;
        hsplit2(oacc[nd][2]*i1, oacc[nd][3]*i1, H, L);
        *(uint32_t*)(oph + (size_t)(r0+8)*DIMM + d) = H;
        *(uint32_t*)(opl + (size_t)(r0+8)*DIMM + d) = L;
    }
}

// ---------------- helpers ----------------
__global__ void split_arr(const float* __restrict__ in, half* __restrict__ h, half* __restrict__ l, int n4){
    int i = blockIdx.x*blockDim.x + threadIdx.x;
    if (i>=n4) return;
    float4 v = ((const float4*)in)[i];
    uint32_t H0,L0,H1,L1;
    hsplit2(v.x, v.y, H0, L0);
    hsplit2(v.z, v.w, H1, L1);
    ((uint2*)h)[i] = make_uint2(H0,H1);
    ((uint2*)l)[i] = make_uint2(L0,L1);
}
__global__ void round_arr(const float* __restrict__ in, half* __restrict__ o, int n4){
    int i = blockIdx.x*blockDim.x + threadIdx.x;
    if (i>=n4) return;
    float4 v = ((const float4*)in)[i];
    ((uint2*)o)[i] = make_uint2(hpack2(v.x,v.y), hpack2(v.z,v.w));
}

extern "C" void kernel_launch(void* const* d_in, const int* in_sizes, int n_in,
                              void* d_out, int out_size){
    const float* x     = (const float*)d_in[0];
    const float* w_qkv = (const float*)d_in[1];
    const float* w_out = (const float*)d_in[2];
    const float* b_out = (const float*)d_in[3];
    float* out = (float*)d_out;

    half *xh,*xl,*wq,*wo,*qf,*kf,*vf,*ah,*al;
    cudaGetSymbolAddress((void**)&xh,g_xh); cudaGetSymbolAddress((void**)&xl,g_xl);
    cudaGetSymbolAddress((void**)&wq,g_wq); cudaGetSymbolAddress((void**)&wo,g_wo);
    cudaGetSymbolAddress((void**)&qf,g_qf);
    cudaGetSymbolAddress((void**)&kf,g_kf); cudaGetSymbolAddress((void**)&vf,g_vf);
    cudaGetSymbolAddress((void**)&ah,g_ah); cudaGetSymbolAddress((void**)&al,g_al);

    cudaFuncSetAttribute(gemm2f<0>, cudaFuncAttributeMaxDynamicSharedMemorySize, 73728);
    cudaFuncSetAttribute(gemm2f<1>, cudaFuncAttributeMaxDynamicSharedMemorySize, 73728);
    cudaFuncSetAttribute(flash_mma, cudaFuncAttributeMaxDynamicSharedMemorySize, 81920);

    split_arr<<<8192*1024/4/256,256>>>(x, xh, xl, 8192*1024/4);
    round_arr<<<3072*1024/4/256,256>>>(w_qkv, wq, 3072*1024/4);
    round_arr<<<1024*1024/4/256,256>>>(w_out, wo, 1024*1024/4);

    // 1) QKV projection -> q (scaled, fp16) / k / v per-head
    gemm2f<1><<<dim3(24,64),256,73728>>>(xh,xl,wq, nullptr,nullptr, qf,kf,vf, 1024, 0);

    // 2) fused flash attention (1-term QK, 1-term PV) -> ah/al
    flash_mma<<<dim3(16,64),256,81920>>>(qf,kf,vf,ah,al);

    // 3) out = att @ w_out^T + b_out
    gemm2f<0><<<dim3(8,64),256,73728>>>(ah,al,wo, out, b_out,
                                        nullptr,nullptr,nullptr, 1024, 1024);
}

// round 10
// speedup vs baseline: 15.9979x; 1.3815x over previous
#include <cuda_runtime.h>
#include <cuda_fp16.h>
#include <cstdint>
#include <cstddef>

#define DIMM 1024
#define NSEQ 2048
#define NB   4
#define NH   16
#define HD   64
#define NBH  (NB*NH)
#define ATTN_SCALE 0.03125f
#define BK 32

__device__ half g_xf[(size_t)NB*NSEQ*DIMM];
__device__ half g_wq[(size_t)3*DIMM*DIMM];
__device__ half g_wo[(size_t)DIMM*DIMM];
__device__ half g_qf[(size_t)NBH*NSEQ*HD];
__device__ half g_kf[(size_t)NBH*NSEQ*HD];
__device__ half g_vf[(size_t)NBH*NSEQ*HD];
__device__ half g_af[(size_t)NB*NSEQ*DIMM];

__device__ __forceinline__ uint32_t s2u(const void* p){
    uint32_t a; asm("{ .reg .u64 t; cvta.to.shared.u64 t, %1; cvt.u32.u64 %0, t; }":"=r"(a):"l"(p)); return a;
}
__device__ __forceinline__ void cp16(uint32_t s, const void* g){
    asm volatile("cp.async.cg.shared.global [%0], [%1], 16;"::"r"(s),"l"(g));
}
#define CPC() asm volatile("cp.async.commit_group;":::"memory")
#define CPW(n) asm volatile("cp.async.wait_group %0;"::"n"(n):"memory")

__device__ __forceinline__ void ldm4(uint32_t* f, uint32_t a){
    asm volatile("ldmatrix.sync.aligned.m8n8.x4.shared.b16 {%0,%1,%2,%3}, [%4];"
        :"=r"(f[0]),"=r"(f[1]),"=r"(f[2]),"=r"(f[3]):"r"(a));
}
__device__ __forceinline__ void ldm4t(uint32_t* f, uint32_t a){
    asm volatile("ldmatrix.sync.aligned.m8n8.x4.trans.shared.b16 {%0,%1,%2,%3}, [%4];"
        :"=r"(f[0]),"=r"(f[1]),"=r"(f[2]),"=r"(f[3]):"r"(a));
}
__device__ __forceinline__ void mma16816(float* d, const uint32_t* a, uint32_t b0, uint32_t b1){
    asm volatile("mma.sync.aligned.m16n8k16.row.col.f32.f16.f16.f32 "
        "{%0,%1,%2,%3}, {%4,%5,%6,%7}, {%8,%9}, {%0,%1,%2,%3};"
        :"+f"(d[0]),"+f"(d[1]),"+f"(d[2]),"+f"(d[3])
        :"r"(a[0]),"r"(a[1]),"r"(a[2]),"r"(a[3]),"r"(b0),"r"(b1));
}
__device__ __forceinline__ uint32_t hpack2(float a, float b){
    __half2 h = __floats2half2_rn(a, b);
    return *(uint32_t*)&h;
}

// ---------------- 1-term fp16 GEMM (NT), 3-stage cp.async pipeline ----------------
// C = Af . Bf^T. 128x128 tile, BK=32, 8 warps (4x2), warp tile 32x64.
// MODE 0: fp32 C (+bias). MODE 1: write q (scaled)/k/v per-head fp16.
template<int MODE>
__global__ __launch_bounds__(256, 2)
void gemm1f(const half* __restrict__ Af, const half* __restrict__ Bf,
            float* __restrict__ C, const float* __restrict__ bias,
            half* __restrict__ qf, half* __restrict__ kf, half* __restrict__ vf,
            int K, int ldc){
    constexpr int STAGE = 16384;   // A 8K | B 8K
    extern __shared__ __align__(256) char smem[];
    const uint32_t su = s2u(smem);

    const int tid = threadIdx.x, lane = tid&31, warp = tid>>5;
    const int wm = warp&3, wn = warp>>2;
    const int bn0 = blockIdx.x*128, bm0 = blockIdx.y*128;
    const size_t lda = (size_t)K*2;

    const char* A0 = (const char*)(Af + (size_t)bm0*K);
    const char* B0 = (const char*)(Bf + (size_t)bn0*K);
    const int CK = K/BK;

    float acc[2][8][4];
#pragma unroll
    for (int i=0;i<2;i++)
#pragma unroll
        for (int j=0;j<8;j++)
#pragma unroll
            for (int k=0;k<4;k++) acc[i][j][k] = 0.f;

    auto load = [&](int t, int s){
        const uint32_t u = su + s*STAGE;
        const size_t ko = (size_t)t*64;
#pragma unroll
        for (int i=0;i<2;i++){ int id=tid+i*256, r=id>>2, c=id&3;
            uint32_t off = r*64 + ((c^((r>>1)&3))<<4);
            size_t g = (size_t)r*lda + c*16 + ko;
            cp16(u + off,        A0 + g);
            cp16(u + 8192 + off, B0 + g); }
    };

    load(0,0); CPC();
    load(1,1); CPC();
    for (int t=0; t<CK; t++){
        if (t+1<CK){ CPW(1); } else { CPW(0); }
        __syncthreads();
        const uint32_t u = su + (t%3)*STAGE;
        const int q = lane>>3, sub = lane&7;
#pragma unroll
        for (int ks=0; ks<2; ks++){
            uint32_t af[2][4];
            const int ch = ks*2 + (q>>1);
#pragma unroll
            for (int mt=0; mt<2; mt++){
                int r = wm*32 + mt*16 + (q&1)*8 + sub;
                ldm4(af[mt], u + r*64 + ((ch^((r>>1)&3))<<4));
            }
#pragma unroll
            for (int np=0; np<4; np++){
                int r = wn*64 + np*16 + (q&1)*8 + sub;
                uint32_t bfh[4];
                ldm4(bfh, u + 8192 + r*64 + ((ch^((r>>1)&3))<<4));
#pragma unroll
                for (int nn=0; nn<2; nn++){
                    const int nt = 2*np + nn;
#pragma unroll
                    for (int mt=0; mt<2; mt++)
                        mma16816(acc[mt][nt], af[mt], bfh[nn], bfh[2+nn]);
                }
            }
        }
        if (t+2<CK){ load(t+2, (t+2)%3); CPC(); }
    }

#pragma unroll
    for (int mt=0; mt<2; mt++){
        const int m0 = bm0 + wm*32 + mt*16 + (lane>>2);
#pragma unroll
        for (int nt=0; nt<8; nt++){
            const int n = bn0 + wn*64 + nt*8 + (lane&3)*2;
            if (MODE == 0){
                float bx = 0.f, by = 0.f;
                if (bias){ bx = bias[n]; by = bias[n+1]; }
                float2 v0 = {acc[mt][nt][0]+bx, acc[mt][nt][1]+by};
                float2 v1 = {acc[mt][nt][2]+bx, acc[mt][nt][3]+by};
                *(float2*)(C + (size_t)m0*ldc + n) = v0;
                *(float2*)(C + (size_t)(m0+8)*ldc + n) = v1;
            } else {
                const int which = n>>10, hh = (n>>6)&15, d = n&63;
                half* D = (which==0) ? qf : (which==1) ? kf : vf;
                const float sc = (which==0) ? ATTN_SCALE : 1.f;
#pragma unroll
                for (int rr=0; rr<2; rr++){
                    const int m = m0 + rr*8;
                    size_t addr = ((size_t)((m>>11)*16 + hh)*2048 + (m&2047))*64 + d;
                    *(uint32_t*)(D + addr) = hpack2(acc[mt][nt][2*rr]*sc, acc[mt][nt][2*rr+1]*sc);
                }
            }
        }
    }
}

// ---------------- fused flash attention, fp16 1-term QK + PV ----------------
// grid (16 qtiles, 64 bh), 256 thr. smem: Qf 16K | 2 x [Kf 16K | Vf 16K] = 80K
__global__ __launch_bounds__(256, 1)
void flash_mma(const half* __restrict__ qf, const half* __restrict__ kf,
               const half* __restrict__ vf, half* __restrict__ of){
    extern __shared__ char sm[];
    const uint32_t su = s2u(sm);
    const uint32_t Qs = su, ST = su + 16384;
    const int tid = threadIdx.x, lane = tid&31, warp = tid>>5;
    const int q2 = lane>>3, sub = lane&7;
    const int qb = blockIdx.x, z = blockIdx.y;

    const char* Qg = (const char*)(qf + ((size_t)z*NSEQ + (size_t)qb*128)*HD);
    const char* Kg = (const char*)(kf + (size_t)z*NSEQ*HD);
    const char* Vg = (const char*)(vf + (size_t)z*NSEQ*HD);

#pragma unroll
    for (int i=0;i<4;i++){ int id=tid+i*256, r=id>>3, c=id&7;
        uint32_t off = r*128 + ((c^(r&7))<<4);
        cp16(Qs+off, Qg + (size_t)id*16); }
    CPC();

    auto loadkv = [&](int t, int s){
        uint32_t b = ST + s*32768;
#pragma unroll
        for (int i=0;i<4;i++){ int id=tid+i*256, r=id>>3, c=id&7;
            uint32_t off = r*128 + ((c^(r&7))<<4);
            size_t g = (size_t)t*16384 + (size_t)id*16;
            cp16(b+off, Kg+g);  cp16(b+16384+off, Vg+g); }
    };
    loadkv(0,0); CPC();

    CPW(1); __syncthreads();
    uint32_t qff[4][4];
    {
        uint32_t rb = (uint32_t)(warp*16 + (q2&1)*8 + sub)*128;
#pragma unroll
        for (int ks=0;ks<4;ks++){
            uint32_t co = (uint32_t)(((ks*2+(q2>>1))^sub)<<4);
            ldm4(qff[ks], Qs + rb + co);
        }
    }

    float m0=-1e30f, m1=-1e30f, l0=0.f, l1=0.f;
    float oacc[8][4];
#pragma unroll
    for (int i=0;i<8;i++){ oacc[i][0]=0.f; oacc[i][1]=0.f; oacc[i][2]=0.f; oacc[i][3]=0.f; }

    const uint32_t krb = (uint32_t)((q2&1)*8+sub)*128;
    const int vrow = ((lane>>3)&1)*8 + (lane&7);
    const int c16b = lane>>4;

    for (int t=0;t<16;t++){
        const int s = t&1;
        if (t<15){ loadkv(t+1, s^1); CPC(); CPW(1); } else { CPW(0); }
        __syncthreads();
        const uint32_t kb = ST + s*32768;

        float sacc[16][4];
#pragma unroll
        for (int i=0;i<16;i++){ sacc[i][0]=0.f; sacc[i][1]=0.f; sacc[i][2]=0.f; sacc[i][3]=0.f; }

#pragma unroll
        for (int ks=0;ks<4;ks++){
            uint32_t bfr[8][4];
            const uint32_t co = (uint32_t)(((ks*2+(q2>>1))^sub)<<4);
#pragma unroll
            for (int g=0;g<8;g++) ldm4(bfr[g], kb + krb + g*2048 + co);
#pragma unroll
            for (int nt=0;nt<16;nt++) mma16816(sacc[nt], qff[ks], bfr[nt>>1][nt&1], bfr[nt>>1][2+(nt&1)]);
        }

        float mt0=-1e30f, mt1=-1e30f;
#pragma unroll
        for (int nt=0;nt<16;nt++){
            mt0 = fmaxf(mt0, fmaxf(sacc[nt][0], sacc[nt][1]));
            mt1 = fmaxf(mt1, fmaxf(sacc[nt][2], sacc[nt][3]));
        }
        mt0 = fmaxf(mt0, __shfl_xor_sync(~0u, mt0, 1));
        mt0 = fmaxf(mt0, __shfl_xor_sync(~0u, mt0, 2));
        mt1 = fmaxf(mt1, __shfl_xor_sync(~0u, mt1, 1));
        mt1 = fmaxf(mt1, __shfl_xor_sync(~0u, mt1, 2));
        float nm0 = fmaxf(m0, mt0), nm1 = fmaxf(m1, mt1);
        float a0 = __expf(m0-nm0), a1 = __expf(m1-nm1);
        m0 = nm0; m1 = nm1;
        float s0=0.f, s1=0.f;
#pragma unroll
        for (int nt=0;nt<16;nt++){
            sacc[nt][0]=__expf(sacc[nt][0]-nm0); s0+=sacc[nt][0];
            sacc[nt][1]=__expf(sacc[nt][1]-nm0); s0+=sacc[nt][1];
            sacc[nt][2]=__expf(sacc[nt][2]-nm1); s1+=sacc[nt][2];
            sacc[nt][3]=__expf(sacc[nt][3]-nm1); s1+=sacc[nt][3];
        }
        s0 += __shfl_xor_sync(~0u,s0,1); s0 += __shfl_xor_sync(~0u,s0,2);
        s1 += __shfl_xor_sync(~0u,s1,1); s1 += __shfl_xor_sync(~0u,s1,2);
        l0 = l0*a0 + s0; l1 = l1*a1 + s1;
#pragma unroll
        for (int nd=0;nd<8;nd++){ oacc[nd][0]*=a0; oacc[nd][1]*=a0; oacc[nd][2]*=a1; oacc[nd][3]*=a1; }

        const uint32_t vb = kb + 16384;
#pragma unroll
        for (int j=0;j<8;j++){
            uint32_t pha[4];
            pha[0] = hpack2(sacc[2*j][0],   sacc[2*j][1]);
            pha[1] = hpack2(sacc[2*j][2],   sacc[2*j][3]);
            pha[2] = hpack2(sacc[2*j+1][0], sacc[2*j+1][1]);
            pha[3] = hpack2(sacc[2*j+1][2], sacc[2*j+1][3]);
            const int row = j*16 + vrow;
#pragma unroll
            for (int pp=0; pp<4; pp++){
                const int c16 = pp*2 + c16b;
                const uint32_t off = (uint32_t)(row*128 + ((c16 ^ (row&7))<<4));
                uint32_t bh4[4];
                ldm4t(bh4, vb + off);
                mma16816(oacc[2*pp],   pha, bh4[0], bh4[1]);
                mma16816(oacc[2*pp+1], pha, bh4[2], bh4[3]);
            }
        }
        __syncthreads();
    }

    const float i0 = 1.f/l0, i1 = 1.f/l1;
    const int r0 = warp*16 + (lane>>2);
    half* op = of + ((size_t)(z>>4)*NSEQ + (size_t)qb*128)*DIMM + (size_t)(z&15)*HD;
#pragma unroll
    for (int nd=0;nd<8;nd++){
        const int d = nd*8 + (lane&3)*2;
        *(uint32_t*)(op + (size_t)r0*DIMM + d)     = hpack2(oacc[nd][0]*i0, oacc[nd][1]*i0);
        *(uint32_t*)(op + (size_t)(r0+8)*DIMM + d) = hpack2(oacc[nd][2]*i1, oacc[nd][3]*i1);
    }
}

// ---------------- helpers ----------------
__global__ void round_arr(const float* __restrict__ in, half* __restrict__ o, int n4){
    int i = blockIdx.x*blockDim.x + threadIdx.x;
    if (i>=n4) return;
    float4 v = ((const float4*)in)[i];
    ((uint2*)o)[i] = make_uint2(hpack2(v.x,v.y), hpack2(v.z,v.w));
}

extern "C" void kernel_launch(void* const* d_in, const int* in_sizes, int n_in,
                              void* d_out, int out_size){
    const float* x     = (const float*)d_in[0];
    const float* w_qkv = (const float*)d_in[1];
    const float* w_out = (const float*)d_in[2];
    const float* b_out = (const float*)d_in[3];
    float* out = (float*)d_out;

    half *xf,*wq,*wo,*qf,*kf,*vf,*af;
    cudaGetSymbolAddress((void**)&xf,g_xf);
    cudaGetSymbolAddress((void**)&wq,g_wq); cudaGetSymbolAddress((void**)&wo,g_wo);
    cudaGetSymbolAddress((void**)&qf,g_qf);
    cudaGetSymbolAddress((void**)&kf,g_kf); cudaGetSymbolAddress((void**)&vf,g_vf);
    cudaGetSymbolAddress((void**)&af,g_af);

    cudaFuncSetAttribute(gemm1f<0>, cudaFuncAttributeMaxDynamicSharedMemorySize, 49152);
    cudaFuncSetAttribute(gemm1f<1>, cudaFuncAttributeMaxDynamicSharedMemorySize, 49152);
    cudaFuncSetAttribute(flash_mma, cudaFuncAttributeMaxDynamicSharedMemorySize, 81920);

    round_arr<<<8192*1024/4/256,256>>>(x, xf, 8192*1024/4);
    round_arr<<<3072*1024/4/256,256>>>(w_qkv, wq, 3072*1024/4);
    round_arr<<<1024*1024/4/256,256>>>(w_out, wo, 1024*1024/4);

    // 1) QKV projection -> q (scaled) / k / v per-head fp16
    gemm1f<1><<<dim3(24,64),256,49152>>>(xf, wq, nullptr, nullptr, qf,kf,vf, 1024, 0);

    // 2) fused flash attention -> af (fp16)
    flash_mma<<<dim3(16,64),256,81920>>>(qf,kf,vf,af);

    // 3) out = att @ w_out^T + b_out
    gemm1f<0><<<dim3(8,64),256,49152>>>(af, wo, out, b_out, nullptr,nullptr,nullptr, 1024, 1024);
}